// round 1
// baseline (speedup 1.0000x reference)
#include <cuda_runtime.h>
#include <cuda_bf16.h>
#include <math.h>

#define B_SZ   512
#define Q_SZ   16384
#define F_DIM  256
#define H_DIM  1024
#define E_DIM  512
#define D_IMG  2048
#define P_POOL 160
#define PER_NEG 32
#define N_NEAR 16
#define N_FAR  16
#define NEAR_CNT 48
#define ROWS_ALL (B_SZ + Q_SZ)

__device__ float g_gps_all[ROWS_ALL * 2];
__device__ float g_ff[ROWS_ALL * (2 * F_DIM)];
__device__ float g_h[ROWS_ALL * H_DIM];
__device__ float g_emb[ROWS_ALL * E_DIM];
__device__ float g_img[B_SZ * E_DIM];
__device__ float g_logits[B_SZ * ROWS_ALL];
__device__ float g_partial[B_SZ];

__global__ void select_kernel(const float* __restrict__ gps,
                              const float* __restrict__ gallery,
                              const int* __restrict__ pool_idx,
                              const int* __restrict__ far_sel,
                              const int* __restrict__ perm) {
    const float DEG = 0.017453292519943295f;
    int b = blockIdx.x;
    int t = threadIdx.x;

    __shared__ float dsm[P_POOL];
    __shared__ float pla[P_POOL], plo[P_POOL];
    __shared__ int order[P_POOL];

    float lat1 = gps[b * 2 + 0] * DEG;
    float lon1 = gps[b * 2 + 1] * DEG;

    if (t < P_POOL) {
        int gi = pool_idx[b * P_POOL + t];
        float la = gallery[gi * 2 + 0];
        float lo = gallery[gi * 2 + 1];
        pla[t] = la; plo[t] = lo;
        float lat2 = la * DEG, lon2 = lo * DEG;
        float sdlat = sinf((lat2 - lat1) * 0.5f);
        float sdlon = sinf((lon2 - lon1) * 0.5f);
        float h = sdlat * sdlat + cosf(lat1) * cosf(lat2) * sdlon * sdlon;
        h = fminf(fmaxf(h, 0.0f), 1.0f);
        dsm[t] = 2.0f * 6371.0f * asinf(sqrtf(h));
    }
    __syncthreads();

    if (t < P_POOL) {
        float dt = dsm[t];
        int r = 0;
        #pragma unroll 8
        for (int j = 0; j < P_POOL; j++) {
            float dj = dsm[j];
            r += (dj < dt) || (dj == dt && j < t);
        }
        order[r] = t;
    }
    __syncthreads();

    if (t < PER_NEG) {
        int s = (t < N_NEAR) ? order[t]
                             : order[NEAR_CNT + far_sel[b * N_FAR + (t - N_NEAR)]];
        int q = b * PER_NEG + t;
        int pos = perm[q];
        g_gps_all[(B_SZ + pos) * 2 + 0] = pla[s];
        g_gps_all[(B_SZ + pos) * 2 + 1] = plo[s];
    }
    if (t < 2) g_gps_all[b * 2 + t] = gps[b * 2 + t];
}

__device__ __forceinline__ unsigned rotl32(unsigned x, int r) {
    return (x << r) | (x >> (32 - r));
}

__device__ __forceinline__ void threefry2x32(unsigned k0, unsigned k1,
                                             unsigned c0, unsigned c1,
                                             unsigned& o0, unsigned& o1) {
    unsigned ks[3] = { k0, k1, 0x1BD11BDAu ^ k0 ^ k1 };
    unsigned x0 = c0 + ks[0];
    unsigned x1 = c1 + ks[1];
    const int R0[4] = {13, 15, 26, 6};
    const int R1[4] = {17, 29, 16, 24};
    #pragma unroll
    for (int i = 0; i < 5; i++) {
        const int* R = (i & 1) ? R1 : R0;
        #pragma unroll
        for (int j = 0; j < 4; j++) {
            x0 += x1;
            x1 = rotl32(x1, R[j]);
            x1 ^= x0;
        }
        x0 += ks[(i + 1) % 3];
        x1 += ks[(i + 2) % 3] + (unsigned)(i + 1);
    }
    o0 = x0; o1 = x1;
}

__device__ __forceinline__ float erfinv_xla(float x) {
    float w = -log1pf(-x * x);
    float p;
    if (w < 5.0f) {
        w -= 2.5f;
        p =            2.81022636e-08f;
        p = fmaf(p, w, 3.43273939e-07f);
        p = fmaf(p, w, -3.5233877e-06f);
        p = fmaf(p, w, -4.39150654e-06f);
        p = fmaf(p, w, 0.00021858087f);
        p = fmaf(p, w, -0.00125372503f);
        p = fmaf(p, w, -0.00417768164f);
        p = fmaf(p, w, 0.246640727f);
        p = fmaf(p, w, 1.50140941f);
    } else {
        w = sqrtf(w) - 3.0f;
        p =            -0.000200214257f;
        p = fmaf(p, w, 0.000100950558f);
        p = fmaf(p, w, 0.00134934322f);
        p = fmaf(p, w, -0.00367342844f);
        p = fmaf(p, w, 0.00573950773f);
        p = fmaf(p, w, -0.0076224613f);
        p = fmaf(p, w, 0.00943887047f);
        p = fmaf(p, w, 1.00167406f);
        p = fmaf(p, w, 2.83297682f);
    }
    return p * x;
}

__device__ __forceinline__ float bits_to_normal(unsigned bits) {
    const float lo = -0.99999994f;
    float u01 = __uint_as_float((bits >> 9) | 0x3f800000u) - 1.0f;
    float v = u01 * (1.0f - lo) + lo;
    v = fmaxf(lo, v);
    return 1.4142135623730951f * erfinv_xla(v);
}

__global__ void noise_kernel() {
    const float NOISE_STD = (float)(2500.0 / 111320.0);
    int t = blockIdx.x * blockDim.x + threadIdx.x;
    unsigned o0, o1;
    threefry2x32(0u, 1u, (unsigned)t, (unsigned)(t + Q_SZ), o0, o1);
    g_gps_all[B_SZ * 2 + t]        += bits_to_normal(o0) * NOISE_STD;
    g_gps_all[B_SZ * 2 + t + Q_SZ] += bits_to_normal(o1) * NOISE_STD;
}

__global__ void ff_kernel(const float* __restrict__ freqs) {
    int r = blockIdx.x;
    int j = threadIdx.x;
    float lat = g_gps_all[r * 2 + 0];
    float lon = g_gps_all[r * 2 + 1];
    float ang = lat * freqs[j] + lon * freqs[F_DIM + j];
    g_ff[r * (2 * F_DIM) + j]         = sinf(ang);
    g_ff[r * (2 * F_DIM) + F_DIM + j] = cosf(ang);
}

template<int BM, int BN, int BK, int TM, int TN, bool BT, int EPI>
__global__ void gemm_kernel(const float* __restrict__ A,
                            const float* __restrict__ B,
                            float* __restrict__ C,
                            const float* __restrict__ bias,
                            int M, int N, int K) {
    constexpr int TX = BN / TN;
    constexpr int TY = BM / TM;
    static_assert(TX * TY == 256, "blockDim must be 256");

    __shared__ float As[BK][BM];
    __shared__ float Bs[BK][BN];

    int tid = threadIdx.x;
    int tx = tid % TX, ty = tid / TX;
    int bm = blockIdx.y * BM;
    int bn = blockIdx.x * BN;

    float acc[TM][TN];
    #pragma unroll
    for (int i = 0; i < TM; i++)
        #pragma unroll
        for (int j = 0; j < TN; j++) acc[i][j] = 0.0f;

    for (int k0 = 0; k0 < K; k0 += BK) {
        {
            constexpr int VPR = BK / 4;
            constexpr int RPP = 256 / VPR;
            #pragma unroll
            for (int p = 0; p < BM / RPP; p++) {
                int row = p * RPP + tid / VPR;
                int kc  = (tid % VPR) * 4;
                float4 v = *(const float4*)&A[(size_t)(bm + row) * K + k0 + kc];
                As[kc + 0][row] = v.x;
                As[kc + 1][row] = v.y;
                As[kc + 2][row] = v.z;
                As[kc + 3][row] = v.w;
            }
        }
        if (!BT) {
            constexpr int VPR = BN / 4;
            constexpr int RPP = 256 / VPR;
            #pragma unroll
            for (int p = 0; p < BK / RPP; p++) {
                int kr = p * RPP + tid / VPR;
                int nc = (tid % VPR) * 4;
                *(float4*)&Bs[kr][nc] =
                    *(const float4*)&B[(size_t)(k0 + kr) * N + bn + nc];
            }
        } else {
            constexpr int VPR = BK / 4;
            constexpr int RPP = 256 / VPR;
            #pragma unroll
            for (int p = 0; p < BN / RPP; p++) {
                int row = p * RPP + tid / VPR;
                int kc  = (tid % VPR) * 4;
                float4 v = *(const float4*)&B[(size_t)(bn + row) * K + k0 + kc];
                Bs[kc + 0][row] = v.x;
                Bs[kc + 1][row] = v.y;
                Bs[kc + 2][row] = v.z;
                Bs[kc + 3][row] = v.w;
            }
        }
        __syncthreads();

        #pragma unroll
        for (int k = 0; k < BK; k++) {
            float ra[TM], rb[TN];
            #pragma unroll
            for (int i = 0; i < TM; i++) ra[i] = As[k][ty * TM + i];
            #pragma unroll
            for (int j = 0; j < TN; j++) rb[j] = Bs[k][tx * TN + j];
            #pragma unroll
            for (int i = 0; i < TM; i++)
                #pragma unroll
                for (int j = 0; j < TN; j++)
                    acc[i][j] = fmaf(ra[i], rb[j], acc[i][j]);
        }
        __syncthreads();
    }

    #pragma unroll
    for (int i = 0; i < TM; i++) {
        int row = bm + ty * TM + i;
        #pragma unroll
        for (int j = 0; j < TN; j++) {
            int col = bn + tx * TN + j;
            float v = acc[i][j];
            if (EPI >= 1) {
                v += bias[col];
                if (EPI == 1) v = fmaxf(v, 0.0f);
            }
            C[(size_t)row * N + col] = v;
        }
    }
}

__global__ void l2norm_kernel(float* __restrict__ X) {
    int r = blockIdx.x;
    int t = threadIdx.x;
    float* row = X + (size_t)r * 512;
    float a = row[t], b = row[t + 256];
    float s = a * a + b * b;
    __shared__ float sm[256];
    sm[t] = s;
    __syncthreads();
    for (int o = 128; o > 0; o >>= 1) {
        if (t < o) sm[t] += sm[t + o];
        __syncthreads();
    }
    float inv = 1.0f / sqrtf(sm[0]);
    row[t] = a * inv;
    row[t + 256] = b * inv;
}

__global__ void lse_kernel(const float* __restrict__ scale_ptr) {
    int r = blockIdx.x;
    int t = threadIdx.x;
    float s = scale_ptr[0];
    const float* row = g_logits + (size_t)r * ROWS_ALL;

    float m = -1e30f;
    for (int j = t; j < ROWS_ALL; j += 256) m = fmaxf(m, row[j]);
    __shared__ float sm[256];
    sm[t] = m;
    __syncthreads();
    for (int o = 128; o > 0; o >>= 1) {
        if (t < o) sm[t] = fmaxf(sm[t], sm[t + o]);
        __syncthreads();
    }
    m = sm[0];
    __syncthreads();

    float sum = 0.0f;
    for (int j = t; j < ROWS_ALL; j += 256) sum += expf(s * (row[j] - m));
    sm[t] = sum;
    __syncthreads();
    for (int o = 128; o > 0; o >>= 1) {
        if (t < o) sm[t] += sm[t + o];
        __syncthreads();
    }
    if (t == 0) {
        g_partial[r] = s * (row[r] - m) - logf(sm[0]);
    }
}

__global__ void final_kernel(float* __restrict__ out) {
    int t = threadIdx.x;
    __shared__ float sm[512];
    sm[t] = g_partial[t];
    __syncthreads();
    for (int o = 256; o > 0; o >>= 1) {
        if (t < o) sm[t] += sm[t + o];
        __syncthreads();
    }
    if (t == 0) out[0] = -sm[0] / (float)B_SZ;
}

extern "C" void kernel_launch(void* const* d_in, const int* in_sizes, int n_in,
                              void* d_out, int out_size) {
    const float* imgs        = (const float*)d_in[0];
    const float* gps         = (const float*)d_in[1];
    const float* gallery     = (const float*)d_in[3];
    const float* W_img       = (const float*)d_in[4];
    const float* freqs       = (const float*)d_in[5];
    const float* W1          = (const float*)d_in[6];
    const float* b1          = (const float*)d_in[7];
    const float* W2          = (const float*)d_in[8];
    const float* b2          = (const float*)d_in[9];
    const float* logit_scale = (const float*)d_in[10];
    const int*   pool_idx    = (const int*)d_in[11];
    const int*   far_sel     = (const int*)d_in[12];
    const int*   perm        = (const int*)d_in[13];
    float* out = (float*)d_out;

    void *p_ff, *p_h, *p_emb, *p_img, *p_logits;
    cudaGetSymbolAddress(&p_ff, g_ff);
    cudaGetSymbolAddress(&p_h, g_h);
    cudaGetSymbolAddress(&p_emb, g_emb);
    cudaGetSymbolAddress(&p_img, g_img);
    cudaGetSymbolAddress(&p_logits, g_logits);
    float* ffp  = (float*)p_ff;
    float* hp   = (float*)p_h;
    float* embp = (float*)p_emb;
    float* imgp = (float*)p_img;
    float* logp = (float*)p_logits;

    select_kernel<<<B_SZ, 192>>>(gps, gallery, pool_idx, far_sel, perm);
    noise_kernel<<<Q_SZ / 256, 256>>>();
    ff_kernel<<<ROWS_ALL, 256>>>(freqs);
    gemm_kernel<128, 128, 16, 8, 8, false, 1>
        <<<dim3(H_DIM / 128, ROWS_ALL / 128), 256>>>(ffp, W1, hp, b1,
                                                     ROWS_ALL, H_DIM, 2 * F_DIM);
    gemm_kernel<128, 128, 16, 8, 8, false, 2>
        <<<dim3(E_DIM / 128, ROWS_ALL / 128), 256>>>(hp, W2, embp, b2,
                                                     ROWS_ALL, E_DIM, H_DIM);
    l2norm_kernel<<<ROWS_ALL, 256>>>(embp);
    gemm_kernel<64, 64, 16, 4, 4, false, 0>
        <<<dim3(E_DIM / 64, B_SZ / 64), 256>>>(imgs, W_img, imgp, nullptr,
                                               B_SZ, E_DIM, D_IMG);
    l2norm_kernel<<<B_SZ, 256>>>(imgp);
    gemm_kernel<128, 128, 16, 8, 8, true, 0>
        <<<dim3(ROWS_ALL / 128, B_SZ / 128), 256>>>(imgp, embp, logp, nullptr,
                                                    B_SZ, ROWS_ALL, E_DIM);
    lse_kernel<<<B_SZ, 256>>>(logit_scale);
    final_kernel<<<1, B_SZ>>>(out);
}

// round 3
// speedup vs baseline: 1.0053x; 1.0053x over previous
#include <cuda_runtime.h>
#include <cuda_bf16.h>
#include <math.h>

#define B_SZ   512
#define Q_SZ   16384
#define F_DIM  256
#define H_DIM  1024
#define E_DIM  512
#define D_IMG  2048
#define P_POOL 160
#define PER_NEG 32
#define N_NEAR 16
#define N_FAR  16
#define NEAR_CNT 48
#define ROWS_ALL (B_SZ + Q_SZ)

__device__ float g_gps_all[ROWS_ALL * 2];
__device__ float g_ff[ROWS_ALL * (2 * F_DIM)];
__device__ float g_h[ROWS_ALL * H_DIM];
__device__ float g_emb[ROWS_ALL * E_DIM];
__device__ float g_img[B_SZ * E_DIM];
__device__ float g_logits[B_SZ * ROWS_ALL];
__device__ float g_partial[B_SZ];

// ---------------------------------------------------------------------------
// selection / noise / fourier features (unchanged, verified bit-exact)
// ---------------------------------------------------------------------------
__global__ void select_kernel(const float* __restrict__ gps,
                              const float* __restrict__ gallery,
                              const int* __restrict__ pool_idx,
                              const int* __restrict__ far_sel,
                              const int* __restrict__ perm) {
    const float DEG = 0.017453292519943295f;
    int b = blockIdx.x;
    int t = threadIdx.x;

    __shared__ float dsm[P_POOL];
    __shared__ float pla[P_POOL], plo[P_POOL];
    __shared__ int order[P_POOL];

    float lat1 = gps[b * 2 + 0] * DEG;
    float lon1 = gps[b * 2 + 1] * DEG;

    if (t < P_POOL) {
        int gi = pool_idx[b * P_POOL + t];
        float la = gallery[gi * 2 + 0];
        float lo = gallery[gi * 2 + 1];
        pla[t] = la; plo[t] = lo;
        float lat2 = la * DEG, lon2 = lo * DEG;
        float sdlat = sinf((lat2 - lat1) * 0.5f);
        float sdlon = sinf((lon2 - lon1) * 0.5f);
        float h = sdlat * sdlat + cosf(lat1) * cosf(lat2) * sdlon * sdlon;
        h = fminf(fmaxf(h, 0.0f), 1.0f);
        dsm[t] = 2.0f * 6371.0f * asinf(sqrtf(h));
    }
    __syncthreads();

    if (t < P_POOL) {
        float dt = dsm[t];
        int r = 0;
        #pragma unroll 8
        for (int j = 0; j < P_POOL; j++) {
            float dj = dsm[j];
            r += (dj < dt) || (dj == dt && j < t);
        }
        order[r] = t;
    }
    __syncthreads();

    if (t < PER_NEG) {
        int s = (t < N_NEAR) ? order[t]
                             : order[NEAR_CNT + far_sel[b * N_FAR + (t - N_NEAR)]];
        int q = b * PER_NEG + t;
        int pos = perm[q];
        g_gps_all[(B_SZ + pos) * 2 + 0] = pla[s];
        g_gps_all[(B_SZ + pos) * 2 + 1] = plo[s];
    }
    if (t < 2) g_gps_all[b * 2 + t] = gps[b * 2 + t];
}

__device__ __forceinline__ unsigned rotl32(unsigned x, int r) {
    return (x << r) | (x >> (32 - r));
}

__device__ __forceinline__ void threefry2x32(unsigned k0, unsigned k1,
                                             unsigned c0, unsigned c1,
                                             unsigned& o0, unsigned& o1) {
    unsigned ks[3] = { k0, k1, 0x1BD11BDAu ^ k0 ^ k1 };
    unsigned x0 = c0 + ks[0];
    unsigned x1 = c1 + ks[1];
    const int R0[4] = {13, 15, 26, 6};
    const int R1[4] = {17, 29, 16, 24};
    #pragma unroll
    for (int i = 0; i < 5; i++) {
        const int* R = (i & 1) ? R1 : R0;
        #pragma unroll
        for (int j = 0; j < 4; j++) {
            x0 += x1;
            x1 = rotl32(x1, R[j]);
            x1 ^= x0;
        }
        x0 += ks[(i + 1) % 3];
        x1 += ks[(i + 2) % 3] + (unsigned)(i + 1);
    }
    o0 = x0; o1 = x1;
}

__device__ __forceinline__ float erfinv_xla(float x) {
    float w = -log1pf(-x * x);
    float p;
    if (w < 5.0f) {
        w -= 2.5f;
        p =            2.81022636e-08f;
        p = fmaf(p, w, 3.43273939e-07f);
        p = fmaf(p, w, -3.5233877e-06f);
        p = fmaf(p, w, -4.39150654e-06f);
        p = fmaf(p, w, 0.00021858087f);
        p = fmaf(p, w, -0.00125372503f);
        p = fmaf(p, w, -0.00417768164f);
        p = fmaf(p, w, 0.246640727f);
        p = fmaf(p, w, 1.50140941f);
    } else {
        w = sqrtf(w) - 3.0f;
        p =            -0.000200214257f;
        p = fmaf(p, w, 0.000100950558f);
        p = fmaf(p, w, 0.00134934322f);
        p = fmaf(p, w, -0.00367342844f);
        p = fmaf(p, w, 0.00573950773f);
        p = fmaf(p, w, -0.0076224613f);
        p = fmaf(p, w, 0.00943887047f);
        p = fmaf(p, w, 1.00167406f);
        p = fmaf(p, w, 2.83297682f);
    }
    return p * x;
}

__device__ __forceinline__ float bits_to_normal(unsigned bits) {
    const float lo = -0.99999994f;
    float u01 = __uint_as_float((bits >> 9) | 0x3f800000u) - 1.0f;
    float v = u01 * (1.0f - lo) + lo;
    v = fmaxf(lo, v);
    return 1.4142135623730951f * erfinv_xla(v);
}

__global__ void noise_kernel() {
    const float NOISE_STD = (float)(2500.0 / 111320.0);
    int t = blockIdx.x * blockDim.x + threadIdx.x;
    unsigned o0, o1;
    threefry2x32(0u, 1u, (unsigned)t, (unsigned)(t + Q_SZ), o0, o1);
    g_gps_all[B_SZ * 2 + t]        += bits_to_normal(o0) * NOISE_STD;
    g_gps_all[B_SZ * 2 + t + Q_SZ] += bits_to_normal(o1) * NOISE_STD;
}

__global__ void ff_kernel(const float* __restrict__ freqs) {
    int r = blockIdx.x;
    int j = threadIdx.x;
    float lat = g_gps_all[r * 2 + 0];
    float lon = g_gps_all[r * 2 + 1];
    float ang = lat * freqs[j] + lon * freqs[F_DIM + j];
    g_ff[r * (2 * F_DIM) + j]         = sinf(ang);
    g_ff[r * (2 * F_DIM) + F_DIM + j] = cosf(ang);
}

// ---------------------------------------------------------------------------
// Double-buffered tiled fp32 GEMM.
//   BT=false: B is [K,N] row-major.   BT=true: B is [N,K] row-major (NT).
//   EPI: 0 none, 1 bias+relu, 2 bias
// smem strides padded by +4 floats (keeps 16B alignment, kills the 4-way
// bank conflicts of the transposed stores).
// ---------------------------------------------------------------------------
template<int BM, int BN, int BK, int TM, int TN, bool BT, int EPI>
__global__ void __launch_bounds__(256, 2)
gemm_kernel(const float* __restrict__ A,
            const float* __restrict__ B,
            float* __restrict__ C,
            const float* __restrict__ bias,
            int M, int N, int K) {
    constexpr int TX = BN / TN;
    constexpr int TY = BM / TM;
    static_assert(TX * TY == 256, "blockDim must be 256");
    constexpr int AST = BM + 4;     // padded stride (floats), multiple of 4
    constexpr int BST = BN + 4;

    // A staging: BM*BK/256 floats per thread = PA float4
    constexpr int VPA = BK / 4;            // float4 chunks along K per row
    constexpr int RPA = 256 / VPA;         // rows covered per pass
    constexpr int PA  = BM / RPA;          // passes
    // B staging
    constexpr int VPB_N = BN / 4;          // !BT: float4 along N
    constexpr int RPB_N = 256 / VPB_N;
    constexpr int PB_N  = BK / RPB_N;
    constexpr int VPB_T = BK / 4;          // BT: float4 along K
    constexpr int RPB_T = 256 / VPB_T;
    constexpr int PB_T  = BN / RPB_T;
    constexpr int PB = BT ? PB_T : PB_N;

    __shared__ float As[2][BK * AST];
    __shared__ float Bs[2][BK * BST];

    int tid = threadIdx.x;
    int tx = tid % TX, ty = tid / TX;
    int bm = blockIdx.y * BM;
    int bn = blockIdx.x * BN;

    float acc[TM][TN];
    #pragma unroll
    for (int i = 0; i < TM; i++)
        #pragma unroll
        for (int j = 0; j < TN; j++) acc[i][j] = 0.0f;

    float4 ar[PA];
    float4 br[PB];

    // precomputed per-thread load offsets
    int a_row = tid / VPA;            // + p*RPA
    int a_kc  = (tid % VPA) * 4;
    int bn_kr = tid / VPB_N;          // + p*RPB_N   (!BT)
    int bn_nc = (tid % VPB_N) * 4;
    int bt_row = tid / VPB_T;         // + p*RPB_T   (BT)
    int bt_kc  = (tid % VPB_T) * 4;

    auto load_regs = [&](int k0) {
        #pragma unroll
        for (int p = 0; p < PA; p++) {
            int row = p * RPA + a_row;
            ar[p] = *(const float4*)&A[(size_t)(bm + row) * K + k0 + a_kc];
        }
        if (!BT) {
            #pragma unroll
            for (int p = 0; p < PB; p++) {
                int kr = p * RPB_N + bn_kr;
                br[p] = *(const float4*)&B[(size_t)(k0 + kr) * N + bn + bn_nc];
            }
        } else {
            #pragma unroll
            for (int p = 0; p < PB; p++) {
                int row = p * RPB_T + bt_row;
                br[p] = *(const float4*)&B[(size_t)(bn + row) * K + k0 + bt_kc];
            }
        }
    };

    auto store_smem = [&](int buf) {
        float* as = As[buf];
        float* bs = Bs[buf];
        #pragma unroll
        for (int p = 0; p < PA; p++) {
            int row = p * RPA + a_row;
            as[(a_kc + 0) * AST + row] = ar[p].x;
            as[(a_kc + 1) * AST + row] = ar[p].y;
            as[(a_kc + 2) * AST + row] = ar[p].z;
            as[(a_kc + 3) * AST + row] = ar[p].w;
        }
        if (!BT) {
            #pragma unroll
            for (int p = 0; p < PB; p++) {
                int kr = p * RPB_N + bn_kr;
                *(float4*)&bs[kr * BST + bn_nc] = br[p];
            }
        } else {
            #pragma unroll
            for (int p = 0; p < PB; p++) {
                int row = p * RPB_T + bt_row;
                bs[(bt_kc + 0) * BST + row] = br[p].x;
                bs[(bt_kc + 1) * BST + row] = br[p].y;
                bs[(bt_kc + 2) * BST + row] = br[p].z;
                bs[(bt_kc + 3) * BST + row] = br[p].w;
            }
        }
    };

    // prologue: tile 0 into buffer 0
    load_regs(0);
    store_smem(0);
    __syncthreads();

    const int ntiles = K / BK;
    int buf = 0;
    for (int t = 0; t < ntiles; t++) {
        if (t + 1 < ntiles) load_regs((t + 1) * BK);

        const float* as = As[buf];
        const float* bs = Bs[buf];
        #pragma unroll
        for (int k = 0; k < BK; k++) {
            float ra[TM], rb[TN];
            #pragma unroll
            for (int i = 0; i < TM; i += 4)
                *(float4*)&ra[i] = *(const float4*)&as[k * AST + ty * TM + i];
            #pragma unroll
            for (int j = 0; j < TN; j += 4)
                *(float4*)&rb[j] = *(const float4*)&bs[k * BST + tx * TN + j];
            #pragma unroll
            for (int i = 0; i < TM; i++)
                #pragma unroll
                for (int j = 0; j < TN; j++)
                    acc[i][j] = fmaf(ra[i], rb[j], acc[i][j]);
        }

        if (t + 1 < ntiles) store_smem(buf ^ 1);
        __syncthreads();
        buf ^= 1;
    }

    #pragma unroll
    for (int i = 0; i < TM; i++) {
        int row = bm + ty * TM + i;
        #pragma unroll
        for (int j = 0; j < TN; j++) {
            int col = bn + tx * TN + j;
            float v = acc[i][j];
            if (EPI >= 1) {
                v += bias[col];
                if (EPI == 1) v = fmaxf(v, 0.0f);
            }
            C[(size_t)row * N + col] = v;
        }
    }
}

// ---------------------------------------------------------------------------
__global__ void l2norm_kernel(float* __restrict__ X) {
    int r = blockIdx.x;
    int t = threadIdx.x;
    float* row = X + (size_t)r * 512;
    float a = row[t], b = row[t + 256];
    float s = a * a + b * b;
    __shared__ float sm[256];
    sm[t] = s;
    __syncthreads();
    for (int o = 128; o > 0; o >>= 1) {
        if (t < o) sm[t] += sm[t + o];
        __syncthreads();
    }
    float inv = 1.0f / sqrtf(sm[0]);
    row[t] = a * inv;
    row[t + 256] = b * inv;
}

__global__ void lse_kernel(const float* __restrict__ scale_ptr) {
    int r = blockIdx.x;
    int t = threadIdx.x;
    float s = scale_ptr[0];
    const float* row = g_logits + (size_t)r * ROWS_ALL;

    float m = -1e30f;
    for (int j = t; j < ROWS_ALL; j += 256) m = fmaxf(m, row[j]);
    __shared__ float sm[256];
    sm[t] = m;
    __syncthreads();
    for (int o = 128; o > 0; o >>= 1) {
        if (t < o) sm[t] = fmaxf(sm[t], sm[t + o]);
        __syncthreads();
    }
    m = sm[0];
    __syncthreads();

    float sum = 0.0f;
    for (int j = t; j < ROWS_ALL; j += 256) sum += expf(s * (row[j] - m));
    sm[t] = sum;
    __syncthreads();
    for (int o = 128; o > 0; o >>= 1) {
        if (t < o) sm[t] += sm[t + o];
        __syncthreads();
    }
    if (t == 0) {
        g_partial[r] = s * (row[r] - m) - logf(sm[0]);
    }
}

__global__ void final_kernel(float* __restrict__ out) {
    int t = threadIdx.x;
    __shared__ float sm[512];
    sm[t] = g_partial[t];
    __syncthreads();
    for (int o = 256; o > 0; o >>= 1) {
        if (t < o) sm[t] += sm[t + o];
        __syncthreads();
    }
    if (t == 0) out[0] = -sm[0] / (float)B_SZ;
}

extern "C" void kernel_launch(void* const* d_in, const int* in_sizes, int n_in,
                              void* d_out, int out_size) {
    const float* imgs        = (const float*)d_in[0];
    const float* gps         = (const float*)d_in[1];
    const float* gallery     = (const float*)d_in[3];
    const float* W_img       = (const float*)d_in[4];
    const float* freqs       = (const float*)d_in[5];
    const float* W1          = (const float*)d_in[6];
    const float* b1          = (const float*)d_in[7];
    const float* W2          = (const float*)d_in[8];
    const float* b2          = (const float*)d_in[9];
    const float* logit_scale = (const float*)d_in[10];
    const int*   pool_idx    = (const int*)d_in[11];
    const int*   far_sel     = (const int*)d_in[12];
    const int*   perm        = (const int*)d_in[13];
    float* out = (float*)d_out;

    void *p_ff, *p_h, *p_emb, *p_img, *p_logits;
    cudaGetSymbolAddress(&p_ff, g_ff);
    cudaGetSymbolAddress(&p_h, g_h);
    cudaGetSymbolAddress(&p_emb, g_emb);
    cudaGetSymbolAddress(&p_img, g_img);
    cudaGetSymbolAddress(&p_logits, g_logits);
    float* ffp  = (float*)p_ff;
    float* hp   = (float*)p_h;
    float* embp = (float*)p_emb;
    float* imgp = (float*)p_img;
    float* logp = (float*)p_logits;

    select_kernel<<<B_SZ, 192>>>(gps, gallery, pool_idx, far_sel, perm);
    noise_kernel<<<Q_SZ / 256, 256>>>();
    ff_kernel<<<ROWS_ALL, 256>>>(freqs);
    // h = relu(ff @ W1 + b1)     [16896,512] x [512,1024]
    gemm_kernel<128, 128, 16, 8, 8, false, 1>
        <<<dim3(H_DIM / 128, ROWS_ALL / 128), 256>>>(ffp, W1, hp, b1,
                                                     ROWS_ALL, H_DIM, 2 * F_DIM);
    // emb = h @ W2 + b2          [16896,1024] x [1024,512]
    gemm_kernel<128, 128, 16, 8, 8, false, 2>
        <<<dim3(E_DIM / 128, ROWS_ALL / 128), 256>>>(hp, W2, embp, b2,
                                                     ROWS_ALL, E_DIM, H_DIM);
    l2norm_kernel<<<ROWS_ALL, 256>>>(embp);
    // img_emb = imgs @ W_img     [512,2048] x [2048,512]
    gemm_kernel<64, 64, 16, 4, 4, false, 0>
        <<<dim3(E_DIM / 64, B_SZ / 64), 256>>>(imgs, W_img, imgp, nullptr,
                                               B_SZ, E_DIM, D_IMG);
    l2norm_kernel<<<B_SZ, 256>>>(imgp);
    // logits = img_emb @ emb^T   [512,512] x [16896,512]^T
    gemm_kernel<128, 128, 16, 8, 8, true, 0>
        <<<dim3(ROWS_ALL / 128, B_SZ / 128), 256>>>(imgp, embp, logp, nullptr,
                                                    B_SZ, ROWS_ALL, E_DIM);
    lse_kernel<<<B_SZ, 256>>>(logit_scale);
    final_kernel<<<1, B_SZ>>>(out);
}

// round 5
// speedup vs baseline: 2.4062x; 2.3935x over previous
#include <cuda_runtime.h>
#include <cuda_bf16.h>
#include <math.h>
#include <stdint.h>

#define B_SZ   512
#define Q_SZ   16384
#define F_DIM  256
#define H_DIM  1024
#define E_DIM  512
#define D_IMG  2048
#define P_POOL 160
#define PER_NEG 32
#define N_NEAR 16
#define N_FAR  16
#define NEAR_CNT 48
#define ROWS_ALL (B_SZ + Q_SZ)

__device__ float g_gps_all[ROWS_ALL * 2];
__device__ float g_ff[ROWS_ALL * (2 * F_DIM)];
__device__ float g_h[ROWS_ALL * H_DIM];
__device__ float g_emb[ROWS_ALL * E_DIM];
__device__ float g_img[B_SZ * E_DIM];
__device__ float g_logits[B_SZ * ROWS_ALL];
__device__ float g_partial[B_SZ];
// transposed weights [N, K] row-major
__device__ float g_w1t[H_DIM * (2 * F_DIM)];
__device__ float g_w2t[E_DIM * H_DIM];
__device__ float g_wit[E_DIM * D_IMG];

// ===========================================================================
// helpers
// ===========================================================================
__device__ __forceinline__ uint32_t smem_u32(const void* p) {
    uint32_t a;
    asm("{ .reg .u64 t; cvta.to.shared.u64 t, %1; cvt.u32.u64 %0, t; }"
        : "=r"(a) : "l"(p));
    return a;
}
__device__ __forceinline__ uint32_t cvt_tf32(float x) {
    uint32_t y;
    asm("cvt.rna.tf32.f32 %0, %1;" : "=r"(y) : "f"(x));
    return y;
}
__device__ __forceinline__ void cp_async16(uint32_t dst, const void* src) {
    asm volatile("cp.async.cg.shared.global [%0], [%1], 16;" :: "r"(dst), "l"(src));
}
#define CP_COMMIT() asm volatile("cp.async.commit_group;" ::: "memory")
#define CP_WAIT0()  asm volatile("cp.async.wait_group 0;" ::: "memory")
#define CP_WAIT1()  asm volatile("cp.async.wait_group 1;" ::: "memory")

__device__ __forceinline__ void mma_tf32(float* c, const uint32_t* a, const uint32_t* b) {
    asm volatile(
        "mma.sync.aligned.m16n8k8.row.col.f32.tf32.tf32.f32 "
        "{%0,%1,%2,%3}, {%4,%5,%6,%7}, {%8,%9}, {%0,%1,%2,%3};"
        : "+f"(c[0]), "+f"(c[1]), "+f"(c[2]), "+f"(c[3])
        : "r"(a[0]), "r"(a[1]), "r"(a[2]), "r"(a[3]), "r"(b[0]), "r"(b[1]));
}

// ===========================================================================
// selection / noise / fourier features (bit-exact, unchanged)
// ===========================================================================
__global__ void select_kernel(const float* __restrict__ gps,
                              const float* __restrict__ gallery,
                              const int* __restrict__ pool_idx,
                              const int* __restrict__ far_sel,
                              const int* __restrict__ perm) {
    const float DEG = 0.017453292519943295f;
    int b = blockIdx.x;
    int t = threadIdx.x;

    __shared__ float dsm[P_POOL];
    __shared__ float pla[P_POOL], plo[P_POOL];
    __shared__ int order[P_POOL];

    float lat1 = gps[b * 2 + 0] * DEG;
    float lon1 = gps[b * 2 + 1] * DEG;

    if (t < P_POOL) {
        int gi = pool_idx[b * P_POOL + t];
        float la = gallery[gi * 2 + 0];
        float lo = gallery[gi * 2 + 1];
        pla[t] = la; plo[t] = lo;
        float lat2 = la * DEG, lon2 = lo * DEG;
        float sdlat = sinf((lat2 - lat1) * 0.5f);
        float sdlon = sinf((lon2 - lon1) * 0.5f);
        float h = sdlat * sdlat + cosf(lat1) * cosf(lat2) * sdlon * sdlon;
        h = fminf(fmaxf(h, 0.0f), 1.0f);
        dsm[t] = 2.0f * 6371.0f * asinf(sqrtf(h));
    }
    __syncthreads();

    if (t < P_POOL) {
        float dt = dsm[t];
        int r = 0;
        #pragma unroll 8
        for (int j = 0; j < P_POOL; j++) {
            float dj = dsm[j];
            r += (dj < dt) || (dj == dt && j < t);
        }
        order[r] = t;
    }
    __syncthreads();

    if (t < PER_NEG) {
        int s = (t < N_NEAR) ? order[t]
                             : order[NEAR_CNT + far_sel[b * N_FAR + (t - N_NEAR)]];
        int q = b * PER_NEG + t;
        int pos = perm[q];
        g_gps_all[(B_SZ + pos) * 2 + 0] = pla[s];
        g_gps_all[(B_SZ + pos) * 2 + 1] = plo[s];
    }
    if (t < 2) g_gps_all[b * 2 + t] = gps[b * 2 + t];
}

__device__ __forceinline__ unsigned rotl32(unsigned x, int r) {
    return (x << r) | (x >> (32 - r));
}
__device__ __forceinline__ void threefry2x32(unsigned k0, unsigned k1,
                                             unsigned c0, unsigned c1,
                                             unsigned& o0, unsigned& o1) {
    unsigned ks[3] = { k0, k1, 0x1BD11BDAu ^ k0 ^ k1 };
    unsigned x0 = c0 + ks[0];
    unsigned x1 = c1 + ks[1];
    const int R0[4] = {13, 15, 26, 6};
    const int R1[4] = {17, 29, 16, 24};
    #pragma unroll
    for (int i = 0; i < 5; i++) {
        const int* R = (i & 1) ? R1 : R0;
        #pragma unroll
        for (int j = 0; j < 4; j++) {
            x0 += x1;
            x1 = rotl32(x1, R[j]);
            x1 ^= x0;
        }
        x0 += ks[(i + 1) % 3];
        x1 += ks[(i + 2) % 3] + (unsigned)(i + 1);
    }
    o0 = x0; o1 = x1;
}
__device__ __forceinline__ float erfinv_xla(float x) {
    float w = -log1pf(-x * x);
    float p;
    if (w < 5.0f) {
        w -= 2.5f;
        p =            2.81022636e-08f;
        p = fmaf(p, w, 3.43273939e-07f);
        p = fmaf(p, w, -3.5233877e-06f);
        p = fmaf(p, w, -4.39150654e-06f);
        p = fmaf(p, w, 0.00021858087f);
        p = fmaf(p, w, -0.00125372503f);
        p = fmaf(p, w, -0.00417768164f);
        p = fmaf(p, w, 0.246640727f);
        p = fmaf(p, w, 1.50140941f);
    } else {
        w = sqrtf(w) - 3.0f;
        p =            -0.000200214257f;
        p = fmaf(p, w, 0.000100950558f);
        p = fmaf(p, w, 0.00134934322f);
        p = fmaf(p, w, -0.00367342844f);
        p = fmaf(p, w, 0.00573950773f);
        p = fmaf(p, w, -0.0076224613f);
        p = fmaf(p, w, 0.00943887047f);
        p = fmaf(p, w, 1.00167406f);
        p = fmaf(p, w, 2.83297682f);
    }
    return p * x;
}
__device__ __forceinline__ float bits_to_normal(unsigned bits) {
    const float lo = -0.99999994f;
    float u01 = __uint_as_float((bits >> 9) | 0x3f800000u) - 1.0f;
    float v = u01 * (1.0f - lo) + lo;
    v = fmaxf(lo, v);
    return 1.4142135623730951f * erfinv_xla(v);
}
__global__ void noise_kernel() {
    const float NOISE_STD = (float)(2500.0 / 111320.0);
    int t = blockIdx.x * blockDim.x + threadIdx.x;
    unsigned o0, o1;
    threefry2x32(0u, 1u, (unsigned)t, (unsigned)(t + Q_SZ), o0, o1);
    g_gps_all[B_SZ * 2 + t]        += bits_to_normal(o0) * NOISE_STD;
    g_gps_all[B_SZ * 2 + t + Q_SZ] += bits_to_normal(o1) * NOISE_STD;
}
__global__ void ff_kernel(const float* __restrict__ freqs) {
    int r = blockIdx.x;
    int j = threadIdx.x;
    float lat = g_gps_all[r * 2 + 0];
    float lon = g_gps_all[r * 2 + 1];
    float ang = lat * freqs[j] + lon * freqs[F_DIM + j];
    float s, c;
    sincosf(ang, &s, &c);
    g_ff[r * (2 * F_DIM) + j]         = s;
    g_ff[r * (2 * F_DIM) + F_DIM + j] = c;
}

// ===========================================================================
// Weight transpose: out[n*K + k] = in[k*N + n]
// ===========================================================================
__global__ void transpose_kernel(const float* __restrict__ in,
                                 float* __restrict__ out, int K, int N) {
    __shared__ float tile[32][33];
    int k0 = blockIdx.y * 32, n0 = blockIdx.x * 32;
    int tx = threadIdx.x, ty = threadIdx.y; // 32 x 8
    #pragma unroll
    for (int i = 0; i < 32; i += 8)
        tile[ty + i][tx] = in[(size_t)(k0 + ty + i) * N + n0 + tx];
    __syncthreads();
    #pragma unroll
    for (int i = 0; i < 32; i += 8)
        out[(size_t)(n0 + ty + i) * K + k0 + tx] = tile[tx][ty + i];
}

// ===========================================================================
// Tensor-core GEMM via mma.sync tf32:
//   C[M,N] = A[M,K] @ B[N,K]^T   (both K-major row-major)
// BM=128, BN=128, BK=32, 256 threads = 8 warps (2 m x 4 n), warp tile 64x32.
// 2-stage cp.async smem pipeline. cvt.rna.tf32 at smem-read time.
// EPI: 0 none, 1 bias+relu, 2 bias
// ===========================================================================
#define GST 36                     // smem row stride in floats
#define TILE_FLOATS (128 * GST)    // 4608 floats = 18432 B per tile buffer
#define MMA_SMEM_BYTES (4 * TILE_FLOATS * 4 + 512)

template<int EPI>
__global__ void __launch_bounds__(256, 2)
gemm_mma(const float* __restrict__ A, const float* __restrict__ Bm,
         float* __restrict__ C, const float* __restrict__ bias,
         int M, int N, int K) {
    extern __shared__ float sm[];
    float* As[2] = { sm,                  sm + TILE_FLOATS };
    float* Bs[2] = { sm + 2 * TILE_FLOATS, sm + 3 * TILE_FLOATS };
    float* biass = sm + 4 * TILE_FLOATS;

    const int tid  = threadIdx.x;
    const int wid  = tid >> 5;
    const int lane = tid & 31;
    const int gid  = lane >> 2;     // 0..7
    const int tid4 = lane & 3;      // 0..3
    const int wm   = (wid & 1) * 64;
    const int wn   = (wid >> 1) * 32;
    const int bm   = blockIdx.y * 128;
    const int bn   = blockIdx.x * 128;

    if (EPI >= 1 && tid < 128) biass[tid] = bias[bn + tid];

    // per-thread cp.async coordinates: 8 float4/row-group; row = cid/8, c4 = cid%8
    const int l_row = tid >> 3;       // 0..31, +32*it
    const int l_c4  = (tid & 7) * 4;  // float offset in row

    const uint32_t a_dst_base = smem_u32(As[0]);
    const uint32_t b_dst_base = smem_u32(Bs[0]);
    const uint32_t buf_stride = TILE_FLOATS * 4; // bytes

    auto prefetch = [&](int s, int buf) {
        const int kc = s * 32;
        uint32_t ad = a_dst_base + buf * buf_stride;
        uint32_t bd = a_dst_base + 2 * buf_stride + buf * buf_stride; // Bs[buf]
        (void)b_dst_base;
        #pragma unroll
        for (int it = 0; it < 4; it++) {
            int row = it * 32 + l_row;
            cp_async16(ad + (row * GST + l_c4) * 4,
                       &A[(size_t)(bm + row) * K + kc + l_c4]);
            cp_async16(bd + (row * GST + l_c4) * 4,
                       &Bm[(size_t)(bn + row) * K + kc + l_c4]);
        }
        CP_COMMIT();
    };

    float acc[4][4][4];
    #pragma unroll
    for (int mi = 0; mi < 4; mi++)
        #pragma unroll
        for (int ni = 0; ni < 4; ni++)
            #pragma unroll
            for (int j = 0; j < 4; j++) acc[mi][ni][j] = 0.0f;

    const int nst = K >> 5;
    prefetch(0, 0);
    if (nst > 1) prefetch(1, 1);

    for (int s = 0; s < nst; s++) {
        const int buf = s & 1;
        if (s < nst - 1) CP_WAIT1(); else CP_WAIT0();
        __syncthreads();

        const float* as = As[buf];
        const float* bs = Bs[buf];
        #pragma unroll
        for (int kk = 0; kk < 32; kk += 8) {
            uint32_t a[4][4], b[4][2];
            #pragma unroll
            for (int mi = 0; mi < 4; mi++) {
                const float* ap = as + (wm + mi * 16 + gid) * GST + kk + tid4;
                a[mi][0] = cvt_tf32(ap[0]);
                a[mi][1] = cvt_tf32(ap[8 * GST]);
                a[mi][2] = cvt_tf32(ap[4]);
                a[mi][3] = cvt_tf32(ap[8 * GST + 4]);
            }
            #pragma unroll
            for (int ni = 0; ni < 4; ni++) {
                const float* bp = bs + (wn + ni * 8 + gid) * GST + kk + tid4;
                b[ni][0] = cvt_tf32(bp[0]);
                b[ni][1] = cvt_tf32(bp[4]);
            }
            #pragma unroll
            for (int mi = 0; mi < 4; mi++)
                #pragma unroll
                for (int ni = 0; ni < 4; ni++)
                    mma_tf32(acc[mi][ni], a[mi], b[ni]);
        }

        __syncthreads();
        if (s + 2 < nst) prefetch(s + 2, buf);
    }

    // epilogue
    #pragma unroll
    for (int mi = 0; mi < 4; mi++) {
        int r0 = bm + wm + mi * 16 + gid;
        #pragma unroll
        for (int ni = 0; ni < 4; ni++) {
            int coll = wn + ni * 8 + tid4 * 2;   // local col in [0,128)
            int col = bn + coll;
            float v0 = acc[mi][ni][0], v1 = acc[mi][ni][1];
            float v2 = acc[mi][ni][2], v3 = acc[mi][ni][3];
            if (EPI >= 1) {
                float b0 = biass[coll], b1 = biass[coll + 1];
                v0 += b0; v1 += b1; v2 += b0; v3 += b1;
                if (EPI == 1) {
                    v0 = fmaxf(v0, 0.0f); v1 = fmaxf(v1, 0.0f);
                    v2 = fmaxf(v2, 0.0f); v3 = fmaxf(v3, 0.0f);
                }
            }
            float2 p01 = { v0, v1 };
            float2 p23 = { v2, v3 };
            *(float2*)&C[(size_t)r0 * N + col] = p01;
            *(float2*)&C[(size_t)(r0 + 8) * N + col] = p23;
        }
    }
}

// ===========================================================================
__global__ void l2norm_kernel(float* __restrict__ X) {
    int r = blockIdx.x;
    int t = threadIdx.x;
    float* row = X + (size_t)r * 512;
    float a = row[t], b = row[t + 256];
    float s = a * a + b * b;
    __shared__ float sm[256];
    sm[t] = s;
    __syncthreads();
    for (int o = 128; o > 0; o >>= 1) {
        if (t < o) sm[t] += sm[t + o];
        __syncthreads();
    }
    float inv = 1.0f / sqrtf(sm[0]);
    row[t] = a * inv;
    row[t + 256] = b * inv;
}

__global__ void lse_kernel(const float* __restrict__ scale_ptr) {
    int r = blockIdx.x;
    int t = threadIdx.x;
    float s = scale_ptr[0];
    const float* row = g_logits + (size_t)r * ROWS_ALL;

    float m = -1e30f;
    for (int j = t; j < ROWS_ALL; j += 256) m = fmaxf(m, row[j]);
    __shared__ float sm[256];
    sm[t] = m;
    __syncthreads();
    for (int o = 128; o > 0; o >>= 1) {
        if (t < o) sm[t] = fmaxf(sm[t], sm[t + o]);
        __syncthreads();
    }
    m = sm[0];
    __syncthreads();

    float sum = 0.0f;
    for (int j = t; j < ROWS_ALL; j += 256) sum += expf(s * (row[j] - m));
    sm[t] = sum;
    __syncthreads();
    for (int o = 128; o > 0; o >>= 1) {
        if (t < o) sm[t] += sm[t + o];
        __syncthreads();
    }
    if (t == 0) {
        g_partial[r] = s * (row[r] - m) - logf(sm[0]);
    }
}

__global__ void final_kernel(float* __restrict__ out) {
    int t = threadIdx.x;
    __shared__ float sm[512];
    sm[t] = g_partial[t];
    __syncthreads();
    for (int o = 256; o > 0; o >>= 1) {
        if (t < o) sm[t] += sm[t + o];
        __syncthreads();
    }
    if (t == 0) out[0] = -sm[0] / (float)B_SZ;
}

// ===========================================================================
extern "C" void kernel_launch(void* const* d_in, const int* in_sizes, int n_in,
                              void* d_out, int out_size) {
    const float* imgs        = (const float*)d_in[0];
    const float* gps         = (const float*)d_in[1];
    const float* gallery     = (const float*)d_in[3];
    const float* W_img       = (const float*)d_in[4];
    const float* freqs       = (const float*)d_in[5];
    const float* W1          = (const float*)d_in[6];
    const float* b1          = (const float*)d_in[7];
    const float* W2          = (const float*)d_in[8];
    const float* b2          = (const float*)d_in[9];
    const float* logit_scale = (const float*)d_in[10];
    const int*   pool_idx    = (const int*)d_in[11];
    const int*   far_sel     = (const int*)d_in[12];
    const int*   perm        = (const int*)d_in[13];
    float* out = (float*)d_out;

    void *p_ff, *p_h, *p_emb, *p_img, *p_logits, *p_w1t, *p_w2t, *p_wit;
    cudaGetSymbolAddress(&p_ff, g_ff);
    cudaGetSymbolAddress(&p_h, g_h);
    cudaGetSymbolAddress(&p_emb, g_emb);
    cudaGetSymbolAddress(&p_img, g_img);
    cudaGetSymbolAddress(&p_logits, g_logits);
    cudaGetSymbolAddress(&p_w1t, g_w1t);
    cudaGetSymbolAddress(&p_w2t, g_w2t);
    cudaGetSymbolAddress(&p_wit, g_wit);
    float* ffp  = (float*)p_ff;
    float* hp   = (float*)p_h;
    float* embp = (float*)p_emb;
    float* imgp = (float*)p_img;
    float* logp = (float*)p_logits;
    float* w1t  = (float*)p_w1t;
    float* w2t  = (float*)p_w2t;
    float* wit  = (float*)p_wit;

    cudaFuncSetAttribute(gemm_mma<0>, cudaFuncAttributeMaxDynamicSharedMemorySize, MMA_SMEM_BYTES);
    cudaFuncSetAttribute(gemm_mma<1>, cudaFuncAttributeMaxDynamicSharedMemorySize, MMA_SMEM_BYTES);
    cudaFuncSetAttribute(gemm_mma<2>, cudaFuncAttributeMaxDynamicSharedMemorySize, MMA_SMEM_BYTES);

    select_kernel<<<B_SZ, 192>>>(gps, gallery, pool_idx, far_sel, perm);
    noise_kernel<<<Q_SZ / 256, 256>>>();
    ff_kernel<<<ROWS_ALL, 256>>>(freqs);

    // weight transposes to [N, K]
    transpose_kernel<<<dim3(H_DIM / 32, (2 * F_DIM) / 32), dim3(32, 8)>>>(W1, w1t, 2 * F_DIM, H_DIM);
    transpose_kernel<<<dim3(E_DIM / 32, H_DIM / 32), dim3(32, 8)>>>(W2, w2t, H_DIM, E_DIM);
    transpose_kernel<<<dim3(E_DIM / 32, D_IMG / 32), dim3(32, 8)>>>(W_img, wit, D_IMG, E_DIM);

    // h = relu(ff @ W1 + b1)        [16896,512] x [1024,512]^T
    gemm_mma<1><<<dim3(H_DIM / 128, ROWS_ALL / 128), 256, MMA_SMEM_BYTES>>>(
        ffp, w1t, hp, b1, ROWS_ALL, H_DIM, 2 * F_DIM);
    // emb = h @ W2 + b2             [16896,1024] x [512,1024]^T
    gemm_mma<2><<<dim3(E_DIM / 128, ROWS_ALL / 128), 256, MMA_SMEM_BYTES>>>(
        hp, w2t, embp, b2, ROWS_ALL, E_DIM, H_DIM);
    l2norm_kernel<<<ROWS_ALL, 256>>>(embp);
    // img_emb = imgs @ W_img        [512,2048] x [512,2048]^T
    gemm_mma<0><<<dim3(E_DIM / 128, B_SZ / 128), 256, MMA_SMEM_BYTES>>>(
        imgs, wit, imgp, nullptr, B_SZ, E_DIM, D_IMG);
    l2norm_kernel<<<B_SZ, 256>>>(imgp);
    // logits = img_emb @ emb^T      [512,512] x [16896,512]^T
    gemm_mma<0><<<dim3(ROWS_ALL / 128, B_SZ / 128), 256, MMA_SMEM_BYTES>>>(
        imgp, embp, logp, nullptr, B_SZ, ROWS_ALL, E_DIM);

    lse_kernel<<<B_SZ, 256>>>(logit_scale);
    final_kernel<<<1, B_SZ>>>(out);
}

// round 6
// speedup vs baseline: 4.8574x; 2.0187x over previous
#include <cuda_runtime.h>
#include <cuda_fp16.h>
#include <math.h>
#include <stdint.h>

#define B_SZ   512
#define Q_SZ   16384
#define F_DIM  256
#define H_DIM  1024
#define E_DIM  512
#define D_IMG  2048
#define P_POOL 160
#define PER_NEG 32
#define N_NEAR 16
#define N_FAR  16
#define NEAR_CNT 48
#define ROWS_ALL (B_SZ + 16384)
#define IMG_SPLITS 8

__device__ float  g_gps_all[ROWS_ALL * 2];
__device__ float  g_partial[B_SZ];
__device__ float  g_logits[B_SZ * ROWS_ALL];
__device__ float  g_emb[ROWS_ALL * E_DIM];          // f32 pre-norm
__device__ float  g_img[B_SZ * E_DIM];              // f32 pre-norm (after reduce)
__device__ float  g_imgpart[IMG_SPLITS * B_SZ * E_DIM];
// fp16 GEMM operands
__device__ __half g_ff_h[ROWS_ALL * (2 * F_DIM)];
__device__ __half g_h_h[ROWS_ALL * H_DIM];
__device__ __half g_emb_h[ROWS_ALL * E_DIM];
__device__ __half g_img_h[B_SZ * E_DIM];
__device__ __half g_imgs_h[B_SZ * D_IMG];
__device__ __half g_w1t_h[H_DIM * (2 * F_DIM)];
__device__ __half g_w2t_h[E_DIM * H_DIM];
__device__ __half g_wit_h[E_DIM * D_IMG];

// ===========================================================================
// helpers
// ===========================================================================
__device__ __forceinline__ uint32_t smem_u32(const void* p) {
    uint32_t a;
    asm("{ .reg .u64 t; cvta.to.shared.u64 t, %1; cvt.u32.u64 %0, t; }"
        : "=r"(a) : "l"(p));
    return a;
}
__device__ __forceinline__ void cp_async16(uint32_t dst, const void* src) {
    asm volatile("cp.async.cg.shared.global [%0], [%1], 16;" :: "r"(dst), "l"(src));
}
#define CP_COMMIT() asm volatile("cp.async.commit_group;" ::: "memory")
#define CP_WAIT0()  asm volatile("cp.async.wait_group 0;" ::: "memory")
#define CP_WAIT1()  asm volatile("cp.async.wait_group 1;" ::: "memory")

__device__ __forceinline__ void mma_f16(float* c, const uint32_t* a, const uint32_t* b) {
    asm volatile(
        "mma.sync.aligned.m16n8k16.row.col.f32.f16.f16.f32 "
        "{%0,%1,%2,%3}, {%4,%5,%6,%7}, {%8,%9}, {%0,%1,%2,%3};"
        : "+f"(c[0]), "+f"(c[1]), "+f"(c[2]), "+f"(c[3])
        : "r"(a[0]), "r"(a[1]), "r"(a[2]), "r"(a[3]), "r"(b[0]), "r"(b[1]));
}

// ===========================================================================
// selection / noise (bit-exact, unchanged)
// ===========================================================================
__global__ void select_kernel(const float* __restrict__ gps,
                              const float* __restrict__ gallery,
                              const int* __restrict__ pool_idx,
                              const int* __restrict__ far_sel,
                              const int* __restrict__ perm) {
    const float DEG = 0.017453292519943295f;
    int b = blockIdx.x;
    int t = threadIdx.x;

    __shared__ float dsm[P_POOL];
    __shared__ float pla[P_POOL], plo[P_POOL];
    __shared__ int order[P_POOL];

    float lat1 = gps[b * 2 + 0] * DEG;
    float lon1 = gps[b * 2 + 1] * DEG;

    if (t < P_POOL) {
        int gi = pool_idx[b * P_POOL + t];
        float la = gallery[gi * 2 + 0];
        float lo = gallery[gi * 2 + 1];
        pla[t] = la; plo[t] = lo;
        float lat2 = la * DEG, lon2 = lo * DEG;
        float sdlat = sinf((lat2 - lat1) * 0.5f);
        float sdlon = sinf((lon2 - lon1) * 0.5f);
        float h = sdlat * sdlat + cosf(lat1) * cosf(lat2) * sdlon * sdlon;
        h = fminf(fmaxf(h, 0.0f), 1.0f);
        dsm[t] = 2.0f * 6371.0f * asinf(sqrtf(h));
    }
    __syncthreads();

    if (t < P_POOL) {
        float dt = dsm[t];
        int r = 0;
        #pragma unroll 8
        for (int j = 0; j < P_POOL; j++) {
            float dj = dsm[j];
            r += (dj < dt) || (dj == dt && j < t);
        }
        order[r] = t;
    }
    __syncthreads();

    if (t < PER_NEG) {
        int s = (t < N_NEAR) ? order[t]
                             : order[NEAR_CNT + far_sel[b * N_FAR + (t - N_NEAR)]];
        int q = b * PER_NEG + t;
        int pos = perm[q];
        g_gps_all[(B_SZ + pos) * 2 + 0] = pla[s];
        g_gps_all[(B_SZ + pos) * 2 + 1] = plo[s];
    }
    if (t < 2) g_gps_all[b * 2 + t] = gps[b * 2 + t];
}

__device__ __forceinline__ unsigned rotl32(unsigned x, int r) {
    return (x << r) | (x >> (32 - r));
}
__device__ __forceinline__ void threefry2x32(unsigned k0, unsigned k1,
                                             unsigned c0, unsigned c1,
                                             unsigned& o0, unsigned& o1) {
    unsigned ks[3] = { k0, k1, 0x1BD11BDAu ^ k0 ^ k1 };
    unsigned x0 = c0 + ks[0];
    unsigned x1 = c1 + ks[1];
    const int R0[4] = {13, 15, 26, 6};
    const int R1[4] = {17, 29, 16, 24};
    #pragma unroll
    for (int i = 0; i < 5; i++) {
        const int* R = (i & 1) ? R1 : R0;
        #pragma unroll
        for (int j = 0; j < 4; j++) {
            x0 += x1;
            x1 = rotl32(x1, R[j]);
            x1 ^= x0;
        }
        x0 += ks[(i + 1) % 3];
        x1 += ks[(i + 2) % 3] + (unsigned)(i + 1);
    }
    o0 = x0; o1 = x1;
}
__device__ __forceinline__ float erfinv_xla(float x) {
    float w = -log1pf(-x * x);
    float p;
    if (w < 5.0f) {
        w -= 2.5f;
        p =            2.81022636e-08f;
        p = fmaf(p, w, 3.43273939e-07f);
        p = fmaf(p, w, -3.5233877e-06f);
        p = fmaf(p, w, -4.39150654e-06f);
        p = fmaf(p, w, 0.00021858087f);
        p = fmaf(p, w, -0.00125372503f);
        p = fmaf(p, w, -0.00417768164f);
        p = fmaf(p, w, 0.246640727f);
        p = fmaf(p, w, 1.50140941f);
    } else {
        w = sqrtf(w) - 3.0f;
        p =            -0.000200214257f;
        p = fmaf(p, w, 0.000100950558f);
        p = fmaf(p, w, 0.00134934322f);
        p = fmaf(p, w, -0.00367342844f);
        p = fmaf(p, w, 0.00573950773f);
        p = fmaf(p, w, -0.0076224613f);
        p = fmaf(p, w, 0.00943887047f);
        p = fmaf(p, w, 1.00167406f);
        p = fmaf(p, w, 2.83297682f);
    }
    return p * x;
}
__device__ __forceinline__ float bits_to_normal(unsigned bits) {
    const float lo = -0.99999994f;
    float u01 = __uint_as_float((bits >> 9) | 0x3f800000u) - 1.0f;
    float v = u01 * (1.0f - lo) + lo;
    v = fmaxf(lo, v);
    return 1.4142135623730951f * erfinv_xla(v);
}
__global__ void noise_kernel() {
    const float NOISE_STD = (float)(2500.0 / 111320.0);
    int t = blockIdx.x * blockDim.x + threadIdx.x;
    unsigned o0, o1;
    threefry2x32(0u, 1u, (unsigned)t, (unsigned)(t + Q_SZ), o0, o1);
    g_gps_all[B_SZ * 2 + t]        += bits_to_normal(o0) * NOISE_STD;
    g_gps_all[B_SZ * 2 + t + Q_SZ] += bits_to_normal(o1) * NOISE_STD;
}

// fourier features -> fp16
__global__ void ff_kernel(const float* __restrict__ freqs) {
    int r = blockIdx.x;
    int j = threadIdx.x;
    float lat = g_gps_all[r * 2 + 0];
    float lon = g_gps_all[r * 2 + 1];
    float ang = lat * freqs[j] + lon * freqs[F_DIM + j];
    float s, c;
    sincosf(ang, &s, &c);
    g_ff_h[r * (2 * F_DIM) + j]         = __float2half_rn(s);
    g_ff_h[r * (2 * F_DIM) + F_DIM + j] = __float2half_rn(c);
}

// transpose f32 -> fp16: out[n*K + k] = in[k*N + n]
__global__ void transpose_half(const float* __restrict__ in,
                               __half* __restrict__ out, int K, int N) {
    __shared__ float tile[32][33];
    int k0 = blockIdx.y * 32, n0 = blockIdx.x * 32;
    int tx = threadIdx.x, ty = threadIdx.y; // 32 x 8
    #pragma unroll
    for (int i = 0; i < 32; i += 8)
        tile[ty + i][tx] = in[(size_t)(k0 + ty + i) * N + n0 + tx];
    __syncthreads();
    #pragma unroll
    for (int i = 0; i < 32; i += 8)
        out[(size_t)(n0 + ty + i) * K + k0 + tx] = __float2half_rn(tile[tx][ty + i]);
}

__global__ void round_half(const float* __restrict__ in, __half* __restrict__ out) {
    int i = blockIdx.x * blockDim.x + threadIdx.x;
    out[i] = __float2half_rn(in[i]);
}

// ===========================================================================
// fp16 tensor-core GEMM: C[M,N] = A[M,K] @ B[N,K]^T
// block 128x128, 8 warps (2m x 4n), warp tile 64x32, BK=32 (2 k16 chunks).
// 2-stage cp.async pipeline. gridDim.z = split-K (A,B offset z*K; C += z*M*N).
// EPI: 0 none(f32), 1 bias+relu (OT), 2 bias (OT)
// ===========================================================================
#define GSTH 40                       // halves per smem row (32 data + 8 pad)
#define TILEH (128 * GSTH)            // halves per tile buffer
#define GEMM_SMEM (4 * TILEH * 2 + 512)

template<int EPI, typename OT>
__global__ void __launch_bounds__(256, 2)
gemm_h(const __half* __restrict__ A, const __half* __restrict__ Bm,
       OT* __restrict__ C, const float* __restrict__ bias,
       int M, int N, int K, int lda, int ldb) {
    extern __shared__ __half smh[];
    __half* Abuf = smh;                       // [2][TILEH]
    __half* Bbuf = smh + 2 * TILEH;           // [2][TILEH]
    float* biass = (float*)(smh + 4 * TILEH);

    const int tid  = threadIdx.x;
    const int wid  = tid >> 5;
    const int lane = tid & 31;
    const int gid  = lane >> 2;
    const int tid4 = lane & 3;
    const int wm   = (wid & 1) * 64;
    const int wn   = (wid >> 1) * 32;
    const int bm   = blockIdx.y * 128;
    const int bn   = blockIdx.x * 128;
    const size_t koff = (size_t)blockIdx.z * K;
    if (blockIdx.z) C += (size_t)blockIdx.z * M * N;

    if (EPI >= 1 && tid < 128) biass[tid] = bias[bn + tid];

    const uint32_t sbase = smem_u32(smh);
    // per-thread cp.async coords: chunk id c in [0,512): row=c/4, 8-half chunk c%4
    const int c_row = tid >> 2;           // 0..63 (+64*it)
    const int c_off = (tid & 3) * 8;      // half offset in row

    auto prefetch = [&](int s, int buf) {
        const int kc = s * 32;
        const uint32_t ad = sbase + (buf * TILEH) * 2;
        const uint32_t bd = sbase + ((2 + buf) * TILEH) * 2;
        #pragma unroll
        for (int it = 0; it < 2; it++) {
            int row = it * 64 + c_row;
            cp_async16(ad + (row * GSTH + c_off) * 2,
                       &A[(size_t)(bm + row) * lda + koff + kc + c_off]);
            cp_async16(bd + (row * GSTH + c_off) * 2,
                       &Bm[(size_t)(bn + row) * ldb + koff + kc + c_off]);
        }
        CP_COMMIT();
    };

    float acc[4][4][4];
    #pragma unroll
    for (int mi = 0; mi < 4; mi++)
        #pragma unroll
        for (int ni = 0; ni < 4; ni++)
            #pragma unroll
            for (int j = 0; j < 4; j++) acc[mi][ni][j] = 0.0f;

    const int nst = K >> 5;
    prefetch(0, 0);
    if (nst > 1) prefetch(1, 1);

    for (int s = 0; s < nst; s++) {
        const int buf = s & 1;
        if (s < nst - 1) CP_WAIT1(); else CP_WAIT0();
        __syncthreads();

        const uint32_t* as = (const uint32_t*)(Abuf + buf * TILEH);
        const uint32_t* bs = (const uint32_t*)(Bbuf + buf * TILEH);
        #pragma unroll
        for (int kc16 = 0; kc16 < 2; kc16++) {
            const int kb = kc16 * 8 + tid4;   // u32 units (GSTH/2 = 20 per row)
            uint32_t a[4][4], b[4][2];
            #pragma unroll
            for (int mi = 0; mi < 4; mi++) {
                int r0 = (wm + mi * 16 + gid) * 20;
                a[mi][0] = as[r0 + kb];
                a[mi][1] = as[r0 + 160 + kb];        // +8 rows
                a[mi][2] = as[r0 + kb + 4];          // k+8
                a[mi][3] = as[r0 + 160 + kb + 4];
            }
            #pragma unroll
            for (int ni = 0; ni < 4; ni++) {
                int r0 = (wn + ni * 8 + gid) * 20;
                b[ni][0] = bs[r0 + kb];
                b[ni][1] = bs[r0 + kb + 4];
            }
            #pragma unroll
            for (int mi = 0; mi < 4; mi++)
                #pragma unroll
                for (int ni = 0; ni < 4; ni++)
                    mma_f16(acc[mi][ni], a[mi], b[ni]);
        }

        __syncthreads();
        if (s + 2 < nst) prefetch(s + 2, buf);
    }

    // epilogue
    #pragma unroll
    for (int mi = 0; mi < 4; mi++) {
        int r0 = bm + wm + mi * 16 + gid;
        #pragma unroll
        for (int ni = 0; ni < 4; ni++) {
            int coll = wn + ni * 8 + tid4 * 2;
            int col = bn + coll;
            float v0 = acc[mi][ni][0], v1 = acc[mi][ni][1];
            float v2 = acc[mi][ni][2], v3 = acc[mi][ni][3];
            if (EPI >= 1) {
                float b0 = biass[coll], b1 = biass[coll + 1];
                v0 += b0; v1 += b1; v2 += b0; v3 += b1;
                if (EPI == 1) {
                    v0 = fmaxf(v0, 0.0f); v1 = fmaxf(v1, 0.0f);
                    v2 = fmaxf(v2, 0.0f); v3 = fmaxf(v3, 0.0f);
                }
            }
            if constexpr (sizeof(OT) == 2) {
                __half2 p01, p23;
                p01.x = __float2half_rn(v0); p01.y = __float2half_rn(v1);
                p23.x = __float2half_rn(v2); p23.y = __float2half_rn(v3);
                *(__half2*)&C[(size_t)r0 * N + col] = p01;
                *(__half2*)&C[(size_t)(r0 + 8) * N + col] = p23;
            } else {
                float2 p01 = { v0, v1 };
                float2 p23 = { v2, v3 };
                *(float2*)&C[(size_t)r0 * N + col] = p01;
                *(float2*)&C[(size_t)(r0 + 8) * N + col] = p23;
            }
        }
    }
}

// deterministic split-K reduce for img GEMM
__global__ void reduce_img() {
    int i = blockIdx.x * blockDim.x + threadIdx.x;   // < 512*512
    float s = 0.0f;
    #pragma unroll
    for (int z = 0; z < IMG_SPLITS; z++)
        s += g_imgpart[(size_t)z * B_SZ * E_DIM + i];
    g_img[i] = s;
}

// l2norm: read f32 rows of 512, write fp16
__global__ void l2norm_half(const float* __restrict__ X, __half* __restrict__ Y) {
    int r = blockIdx.x;
    int t = threadIdx.x;
    const float* row = X + (size_t)r * 512;
    float a = row[t], b = row[t + 256];
    float s = a * a + b * b;
    __shared__ float sm[256];
    sm[t] = s;
    __syncthreads();
    for (int o = 128; o > 0; o >>= 1) {
        if (t < o) sm[t] += sm[t + o];
        __syncthreads();
    }
    float inv = 1.0f / sqrtf(sm[0]);
    Y[(size_t)r * 512 + t]       = __float2half_rn(a * inv);
    Y[(size_t)r * 512 + t + 256] = __float2half_rn(b * inv);
}

__global__ void lse_kernel(const float* __restrict__ scale_ptr) {
    int r = blockIdx.x;
    int t = threadIdx.x;
    float s = scale_ptr[0];
    const float* row = g_logits + (size_t)r * ROWS_ALL;

    float m = -1e30f;
    for (int j = t; j < ROWS_ALL; j += 256) m = fmaxf(m, row[j]);
    __shared__ float sm[256];
    sm[t] = m;
    __syncthreads();
    for (int o = 128; o > 0; o >>= 1) {
        if (t < o) sm[t] = fmaxf(sm[t], sm[t + o]);
        __syncthreads();
    }
    m = sm[0];
    __syncthreads();

    float sum = 0.0f;
    for (int j = t; j < ROWS_ALL; j += 256) sum += expf(s * (row[j] - m));
    sm[t] = sum;
    __syncthreads();
    for (int o = 128; o > 0; o >>= 1) {
        if (t < o) sm[t] += sm[t + o];
        __syncthreads();
    }
    if (t == 0) {
        g_partial[r] = s * (row[r] - m) - logf(sm[0]);
    }
}

__global__ void final_kernel(float* __restrict__ out) {
    int t = threadIdx.x;
    __shared__ float sm[512];
    sm[t] = g_partial[t];
    __syncthreads();
    for (int o = 256; o > 0; o >>= 1) {
        if (t < o) sm[t] += sm[t + o];
        __syncthreads();
    }
    if (t == 0) out[0] = -sm[0] / (float)B_SZ;
}

// ===========================================================================
extern "C" void kernel_launch(void* const* d_in, const int* in_sizes, int n_in,
                              void* d_out, int out_size) {
    const float* imgs        = (const float*)d_in[0];
    const float* gps         = (const float*)d_in[1];
    const float* gallery     = (const float*)d_in[3];
    const float* W_img       = (const float*)d_in[4];
    const float* freqs       = (const float*)d_in[5];
    const float* W1          = (const float*)d_in[6];
    const float* b1          = (const float*)d_in[7];
    const float* W2          = (const float*)d_in[8];
    const float* b2          = (const float*)d_in[9];
    const float* logit_scale = (const float*)d_in[10];
    const int*   pool_idx    = (const int*)d_in[11];
    const int*   far_sel     = (const int*)d_in[12];
    const int*   perm        = (const int*)d_in[13];
    float* out = (float*)d_out;

    void *p_ffh, *p_hh, *p_emb, *p_embh, *p_img, *p_imgh, *p_imgsh;
    void *p_w1t, *p_w2t, *p_wit, *p_logits, *p_part;
    cudaGetSymbolAddress(&p_ffh, g_ff_h);
    cudaGetSymbolAddress(&p_hh, g_h_h);
    cudaGetSymbolAddress(&p_emb, g_emb);
    cudaGetSymbolAddress(&p_embh, g_emb_h);
    cudaGetSymbolAddress(&p_img, g_img);
    cudaGetSymbolAddress(&p_imgh, g_img_h);
    cudaGetSymbolAddress(&p_imgsh, g_imgs_h);
    cudaGetSymbolAddress(&p_w1t, g_w1t_h);
    cudaGetSymbolAddress(&p_w2t, g_w2t_h);
    cudaGetSymbolAddress(&p_wit, g_wit_h);
    cudaGetSymbolAddress(&p_logits, g_logits);
    cudaGetSymbolAddress(&p_part, g_imgpart);
    __half* ffh  = (__half*)p_ffh;
    __half* hh   = (__half*)p_hh;
    float*  embp = (float*)p_emb;
    __half* embh = (__half*)p_embh;
    float*  imgp = (float*)p_img;
    __half* imgh = (__half*)p_imgh;
    __half* imgsh= (__half*)p_imgsh;
    __half* w1t  = (__half*)p_w1t;
    __half* w2t  = (__half*)p_w2t;
    __half* wit  = (__half*)p_wit;
    float*  logp = (float*)p_logits;
    float*  partp= (float*)p_part;

    cudaFuncSetAttribute(gemm_h<0, float>,  cudaFuncAttributeMaxDynamicSharedMemorySize, GEMM_SMEM);
    cudaFuncSetAttribute(gemm_h<1, __half>, cudaFuncAttributeMaxDynamicSharedMemorySize, GEMM_SMEM);
    cudaFuncSetAttribute(gemm_h<2, float>,  cudaFuncAttributeMaxDynamicSharedMemorySize, GEMM_SMEM);

    select_kernel<<<B_SZ, 192>>>(gps, gallery, pool_idx, far_sel, perm);
    noise_kernel<<<Q_SZ / 256, 256>>>();
    ff_kernel<<<ROWS_ALL, 256>>>(freqs);

    transpose_half<<<dim3(H_DIM / 32, (2 * F_DIM) / 32), dim3(32, 8)>>>(W1, w1t, 2 * F_DIM, H_DIM);
    transpose_half<<<dim3(E_DIM / 32, H_DIM / 32), dim3(32, 8)>>>(W2, w2t, H_DIM, E_DIM);
    transpose_half<<<dim3(E_DIM / 32, D_IMG / 32), dim3(32, 8)>>>(W_img, wit, D_IMG, E_DIM);
    round_half<<<(B_SZ * D_IMG) / 256, 256>>>(imgs, imgsh);

    // h = relu(ff @ W1 + b1) -> fp16     [16896,512] x [1024,512]^T
    gemm_h<1, __half><<<dim3(H_DIM / 128, ROWS_ALL / 128, 1), 256, GEMM_SMEM>>>(
        ffh, w1t, hh, b1, ROWS_ALL, H_DIM, 2 * F_DIM, 2 * F_DIM, 2 * F_DIM);
    // emb = h @ W2 + b2 -> f32           [16896,1024] x [512,1024]^T
    gemm_h<2, float><<<dim3(E_DIM / 128, ROWS_ALL / 128, 1), 256, GEMM_SMEM>>>(
        hh, w2t, embp, b2, ROWS_ALL, E_DIM, H_DIM, H_DIM, H_DIM);
    l2norm_half<<<ROWS_ALL, 256>>>(embp, embh);

    // img_emb partials: split-K x8       [512,2048] x [512,2048]^T
    gemm_h<0, float><<<dim3(E_DIM / 128, B_SZ / 128, IMG_SPLITS), 256, GEMM_SMEM>>>(
        imgsh, wit, partp, nullptr, B_SZ, E_DIM, D_IMG / IMG_SPLITS, D_IMG, D_IMG);
    reduce_img<<<(B_SZ * E_DIM) / 256, 256>>>();
    l2norm_half<<<B_SZ, 256>>>(imgp, imgh);

    // logits = img_emb @ emb^T -> f32    [512,512] x [16896,512]^T
    gemm_h<0, float><<<dim3(ROWS_ALL / 128, B_SZ / 128, 1), 256, GEMM_SMEM>>>(
        imgh, embh, logp, nullptr, B_SZ, ROWS_ALL, E_DIM, E_DIM, E_DIM);

    lse_kernel<<<B_SZ, 256>>>(logit_scale);
    final_kernel<<<1, B_SZ>>>(out);
}

// round 7
// speedup vs baseline: 5.1077x; 1.0515x over previous
#include <cuda_runtime.h>
#include <cuda_fp16.h>
#include <math.h>
#include <stdint.h>

#define B_SZ   512
#define Q_SZ   16384
#define F_DIM  256
#define H_DIM  1024
#define E_DIM  512
#define D_IMG  2048
#define P_POOL 160
#define PER_NEG 32
#define N_NEAR 16
#define N_FAR  16
#define NEAR_CNT 48
#define ROWS_ALL (B_SZ + 16384)
#define IMG_SPLITS 8

__device__ float  g_gps_all[ROWS_ALL * 2];
__device__ float  g_partial[B_SZ];
__device__ float  g_logits[B_SZ * ROWS_ALL];
__device__ float  g_emb[ROWS_ALL * E_DIM];
__device__ float  g_img[B_SZ * E_DIM];
__device__ float  g_imgpart[IMG_SPLITS * B_SZ * E_DIM];
__device__ __half g_ff_h[ROWS_ALL * (2 * F_DIM)];
__device__ __half g_h_h[ROWS_ALL * H_DIM];
__device__ __half g_emb_h[ROWS_ALL * E_DIM];
__device__ __half g_img_h[B_SZ * E_DIM];
__device__ __half g_imgs_h[B_SZ * D_IMG];
__device__ __half g_w1t_h[H_DIM * (2 * F_DIM)];
__device__ __half g_w2t_h[E_DIM * H_DIM];
__device__ __half g_wit_h[E_DIM * D_IMG];

// ===========================================================================
// helpers
// ===========================================================================
__device__ __forceinline__ uint32_t smem_u32(const void* p) {
    uint32_t a;
    asm("{ .reg .u64 t; cvta.to.shared.u64 t, %1; cvt.u32.u64 %0, t; }"
        : "=r"(a) : "l"(p));
    return a;
}
__device__ __forceinline__ void cp_async16(uint32_t dst, const void* src) {
    asm volatile("cp.async.cg.shared.global [%0], [%1], 16;" :: "r"(dst), "l"(src));
}
#define CP_COMMIT() asm volatile("cp.async.commit_group;" ::: "memory")
#define CP_WAIT0()  asm volatile("cp.async.wait_group 0;" ::: "memory")
#define CP_WAIT1()  asm volatile("cp.async.wait_group 1;" ::: "memory")

__device__ __forceinline__ void mma_f16(float* c, const uint32_t* a, const uint32_t* b) {
    asm volatile(
        "mma.sync.aligned.m16n8k16.row.col.f32.f16.f16.f32 "
        "{%0,%1,%2,%3}, {%4,%5,%6,%7}, {%8,%9}, {%0,%1,%2,%3};"
        : "+f"(c[0]), "+f"(c[1]), "+f"(c[2]), "+f"(c[3])
        : "r"(a[0]), "r"(a[1]), "r"(a[2]), "r"(a[3]), "r"(b[0]), "r"(b[1]));
}
__device__ __forceinline__ void ldmatrix_x4(uint32_t* r, uint32_t addr) {
    asm volatile("ldmatrix.sync.aligned.m8n8.x4.shared.b16 {%0,%1,%2,%3}, [%4];"
        : "=r"(r[0]), "=r"(r[1]), "=r"(r[2]), "=r"(r[3]) : "r"(addr));
}

// ===========================================================================
// selection / noise (bit-exact, unchanged)
// ===========================================================================
__global__ void select_kernel(const float* __restrict__ gps,
                              const float* __restrict__ gallery,
                              const int* __restrict__ pool_idx,
                              const int* __restrict__ far_sel,
                              const int* __restrict__ perm) {
    const float DEG = 0.017453292519943295f;
    int b = blockIdx.x;
    int t = threadIdx.x;

    __shared__ float dsm[P_POOL];
    __shared__ float pla[P_POOL], plo[P_POOL];
    __shared__ int order[P_POOL];

    float lat1 = gps[b * 2 + 0] * DEG;
    float lon1 = gps[b * 2 + 1] * DEG;

    if (t < P_POOL) {
        int gi = pool_idx[b * P_POOL + t];
        float la = gallery[gi * 2 + 0];
        float lo = gallery[gi * 2 + 1];
        pla[t] = la; plo[t] = lo;
        float lat2 = la * DEG, lon2 = lo * DEG;
        float sdlat = sinf((lat2 - lat1) * 0.5f);
        float sdlon = sinf((lon2 - lon1) * 0.5f);
        float h = sdlat * sdlat + cosf(lat1) * cosf(lat2) * sdlon * sdlon;
        h = fminf(fmaxf(h, 0.0f), 1.0f);
        dsm[t] = 2.0f * 6371.0f * asinf(sqrtf(h));
    }
    __syncthreads();

    if (t < P_POOL) {
        float dt = dsm[t];
        int r = 0;
        #pragma unroll 8
        for (int j = 0; j < P_POOL; j++) {
            float dj = dsm[j];
            r += (dj < dt) || (dj == dt && j < t);
        }
        order[r] = t;
    }
    __syncthreads();

    if (t < PER_NEG) {
        int s = (t < N_NEAR) ? order[t]
                             : order[NEAR_CNT + far_sel[b * N_FAR + (t - N_NEAR)]];
        int q = b * PER_NEG + t;
        int pos = perm[q];
        g_gps_all[(B_SZ + pos) * 2 + 0] = pla[s];
        g_gps_all[(B_SZ + pos) * 2 + 1] = plo[s];
    }
    if (t < 2) g_gps_all[b * 2 + t] = gps[b * 2 + t];
}

__device__ __forceinline__ unsigned rotl32(unsigned x, int r) {
    return (x << r) | (x >> (32 - r));
}
__device__ __forceinline__ void threefry2x32(unsigned k0, unsigned k1,
                                             unsigned c0, unsigned c1,
                                             unsigned& o0, unsigned& o1) {
    unsigned ks[3] = { k0, k1, 0x1BD11BDAu ^ k0 ^ k1 };
    unsigned x0 = c0 + ks[0];
    unsigned x1 = c1 + ks[1];
    const int R0[4] = {13, 15, 26, 6};
    const int R1[4] = {17, 29, 16, 24};
    #pragma unroll
    for (int i = 0; i < 5; i++) {
        const int* R = (i & 1) ? R1 : R0;
        #pragma unroll
        for (int j = 0; j < 4; j++) {
            x0 += x1;
            x1 = rotl32(x1, R[j]);
            x1 ^= x0;
        }
        x0 += ks[(i + 1) % 3];
        x1 += ks[(i + 2) % 3] + (unsigned)(i + 1);
    }
    o0 = x0; o1 = x1;
}
__device__ __forceinline__ float erfinv_xla(float x) {
    float w = -log1pf(-x * x);
    float p;
    if (w < 5.0f) {
        w -= 2.5f;
        p =            2.81022636e-08f;
        p = fmaf(p, w, 3.43273939e-07f);
        p = fmaf(p, w, -3.5233877e-06f);
        p = fmaf(p, w, -4.39150654e-06f);
        p = fmaf(p, w, 0.00021858087f);
        p = fmaf(p, w, -0.00125372503f);
        p = fmaf(p, w, -0.00417768164f);
        p = fmaf(p, w, 0.246640727f);
        p = fmaf(p, w, 1.50140941f);
    } else {
        w = sqrtf(w) - 3.0f;
        p =            -0.000200214257f;
        p = fmaf(p, w, 0.000100950558f);
        p = fmaf(p, w, 0.00134934322f);
        p = fmaf(p, w, -0.00367342844f);
        p = fmaf(p, w, 0.00573950773f);
        p = fmaf(p, w, -0.0076224613f);
        p = fmaf(p, w, 0.00943887047f);
        p = fmaf(p, w, 1.00167406f);
        p = fmaf(p, w, 2.83297682f);
    }
    return p * x;
}
__device__ __forceinline__ float bits_to_normal(unsigned bits) {
    const float lo = -0.99999994f;
    float u01 = __uint_as_float((bits >> 9) | 0x3f800000u) - 1.0f;
    float v = u01 * (1.0f - lo) + lo;
    v = fmaxf(lo, v);
    return 1.4142135623730951f * erfinv_xla(v);
}
__global__ void noise_kernel() {
    const float NOISE_STD = (float)(2500.0 / 111320.0);
    int t = blockIdx.x * blockDim.x + threadIdx.x;
    unsigned o0, o1;
    threefry2x32(0u, 1u, (unsigned)t, (unsigned)(t + Q_SZ), o0, o1);
    g_gps_all[B_SZ * 2 + t]        += bits_to_normal(o0) * NOISE_STD;
    g_gps_all[B_SZ * 2 + t + Q_SZ] += bits_to_normal(o1) * NOISE_STD;
}

// fourier features -> fp16 (fast hw sincos; abs err ~|x|*2^-24 << fp16 rounding)
__global__ void ff_kernel(const float* __restrict__ freqs) {
    int r = blockIdx.x;
    int j = threadIdx.x;
    float lat = g_gps_all[r * 2 + 0];
    float lon = g_gps_all[r * 2 + 1];
    float ang = lat * freqs[j] + lon * freqs[F_DIM + j];
    float s, c;
    __sincosf(ang, &s, &c);
    g_ff_h[r * (2 * F_DIM) + j]         = __float2half_rn(s);
    g_ff_h[r * (2 * F_DIM) + F_DIM + j] = __float2half_rn(c);
}

// transpose f32 -> fp16: out[n*K + k] = in[k*N + n]
__global__ void transpose_half(const float* __restrict__ in,
                               __half* __restrict__ out, int K, int N) {
    __shared__ float tile[32][33];
    int k0 = blockIdx.y * 32, n0 = blockIdx.x * 32;
    int tx = threadIdx.x, ty = threadIdx.y; // 32 x 8
    #pragma unroll
    for (int i = 0; i < 32; i += 8)
        tile[ty + i][tx] = in[(size_t)(k0 + ty + i) * N + n0 + tx];
    __syncthreads();
    #pragma unroll
    for (int i = 0; i < 32; i += 8)
        out[(size_t)(n0 + ty + i) * K + k0 + tx] = __float2half_rn(tile[tx][ty + i]);
}

__global__ void round_half(const float* __restrict__ in, __half* __restrict__ out) {
    int i = blockIdx.x * blockDim.x + threadIdx.x;
    out[i] = __float2half_rn(in[i]);
}

// ===========================================================================
// fp16 tensor-core GEMM, ldmatrix fragment loads.
//   C[M,N] = A[M,K] @ B[N,K]^T
// block 128x128, 8 warps (2m x 4n), warp tile 64x32, BK=32.
// ===========================================================================
#define GSTH 40                       // halves per smem row (80 B; conflict-free)
#define TILEH (128 * GSTH)
#define GEMM_SMEM (4 * TILEH * 2 + 512)

template<int EPI, typename OT>
__global__ void __launch_bounds__(256, 2)
gemm_h(const __half* __restrict__ A, const __half* __restrict__ Bm,
       OT* __restrict__ C, const float* __restrict__ bias,
       int M, int N, int K, int lda, int ldb) {
    extern __shared__ __half smh[];
    float* biass = (float*)(smh + 4 * TILEH);

    const int tid  = threadIdx.x;
    const int wid  = tid >> 5;
    const int lane = tid & 31;
    const int gid  = lane >> 2;
    const int tid4 = lane & 3;
    const int wm   = (wid & 1) * 64;
    const int wn   = (wid >> 1) * 32;
    const int bm   = blockIdx.y * 128;
    const int bn   = blockIdx.x * 128;
    const size_t koff = (size_t)blockIdx.z * K;
    if (blockIdx.z) C += (size_t)blockIdx.z * M * N;

    if (EPI >= 1 && tid < 128) biass[tid] = bias[bn + tid];

    const uint32_t sbase = smem_u32(smh);
    const int c_row = tid >> 2;
    const int c_off = (tid & 3) * 8;

    auto prefetch = [&](int s, int buf) {
        const int kc = s * 32;
        const uint32_t ad = sbase + (buf * TILEH) * 2;
        const uint32_t bd = sbase + ((2 + buf) * TILEH) * 2;
        #pragma unroll
        for (int it = 0; it < 2; it++) {
            int row = it * 64 + c_row;
            cp_async16(ad + (row * GSTH + c_off) * 2,
                       &A[(size_t)(bm + row) * lda + koff + kc + c_off]);
            cp_async16(bd + (row * GSTH + c_off) * 2,
                       &Bm[(size_t)(bn + row) * ldb + koff + kc + c_off]);
        }
        CP_COMMIT();
    };

    // ldmatrix per-lane base addresses
    const int lane7 = lane & 7;
    const int a_row = wm + lane7 + ((lane >> 3) & 1) * 8;   // + mi*16
    const int a_kh  = ((lane >> 4) & 1) * 8;                 // + kc16*16
    const uint32_t a_lm = sbase + (a_row * GSTH + a_kh) * 2;
    const int b_row = wn + lane7 + ((lane >> 4) & 1) * 8;   // + nj*16
    const int b_kh  = ((lane >> 3) & 1) * 8;
    const uint32_t b_lm = sbase + 2 * TILEH * 2 + (b_row * GSTH + b_kh) * 2;

    float acc[4][4][4];
    #pragma unroll
    for (int mi = 0; mi < 4; mi++)
        #pragma unroll
        for (int ni = 0; ni < 4; ni++)
            #pragma unroll
            for (int j = 0; j < 4; j++) acc[mi][ni][j] = 0.0f;

    const int nst = K >> 5;
    prefetch(0, 0);
    if (nst > 1) prefetch(1, 1);

    for (int s = 0; s < nst; s++) {
        const int buf = s & 1;
        if (s < nst - 1) CP_WAIT1(); else CP_WAIT0();
        __syncthreads();

        const uint32_t boff = buf * (TILEH * 2);
        #pragma unroll
        for (int kc16 = 0; kc16 < 2; kc16++) {
            const uint32_t kb = kc16 * 32;   // 16 halves = 32 B
            uint32_t a[4][4], b[4][2];
            #pragma unroll
            for (int mi = 0; mi < 4; mi++)
                ldmatrix_x4(a[mi], a_lm + boff + mi * (16 * GSTH * 2) + kb);
            #pragma unroll
            for (int nj = 0; nj < 2; nj++) {
                uint32_t r[4];
                ldmatrix_x4(r, b_lm + boff + nj * (16 * GSTH * 2) + kb);
                b[2 * nj][0] = r[0]; b[2 * nj][1] = r[1];
                b[2 * nj + 1][0] = r[2]; b[2 * nj + 1][1] = r[3];
            }
            #pragma unroll
            for (int mi = 0; mi < 4; mi++)
                #pragma unroll
                for (int ni = 0; ni < 4; ni++)
                    mma_f16(acc[mi][ni], a[mi], b[ni]);
        }

        __syncthreads();
        if (s + 2 < nst) prefetch(s + 2, buf);
    }

    // epilogue
    #pragma unroll
    for (int mi = 0; mi < 4; mi++) {
        int r0 = bm + wm + mi * 16 + gid;
        #pragma unroll
        for (int ni = 0; ni < 4; ni++) {
            int coll = wn + ni * 8 + tid4 * 2;
            int col = bn + coll;
            float v0 = acc[mi][ni][0], v1 = acc[mi][ni][1];
            float v2 = acc[mi][ni][2], v3 = acc[mi][ni][3];
            if (EPI >= 1) {
                float b0 = biass[coll], b1 = biass[coll + 1];
                v0 += b0; v1 += b1; v2 += b0; v3 += b1;
                if (EPI == 1) {
                    v0 = fmaxf(v0, 0.0f); v1 = fmaxf(v1, 0.0f);
                    v2 = fmaxf(v2, 0.0f); v3 = fmaxf(v3, 0.0f);
                }
            }
            if constexpr (sizeof(OT) == 2) {
                __half2 p01, p23;
                p01.x = __float2half_rn(v0); p01.y = __float2half_rn(v1);
                p23.x = __float2half_rn(v2); p23.y = __float2half_rn(v3);
                *(__half2*)&C[(size_t)r0 * N + col] = p01;
                *(__half2*)&C[(size_t)(r0 + 8) * N + col] = p23;
            } else {
                float2 p01 = { v0, v1 };
                float2 p23 = { v2, v3 };
                *(float2*)&C[(size_t)r0 * N + col] = p01;
                *(float2*)&C[(size_t)(r0 + 8) * N + col] = p23;
            }
        }
    }
}

// deterministic split-K reduce for img GEMM
__global__ void reduce_img() {
    int i = blockIdx.x * blockDim.x + threadIdx.x;
    float s = 0.0f;
    #pragma unroll
    for (int z = 0; z < IMG_SPLITS; z++)
        s += g_imgpart[(size_t)z * B_SZ * E_DIM + i];
    g_img[i] = s;
}

__global__ void l2norm_half(const float* __restrict__ X, __half* __restrict__ Y) {
    int r = blockIdx.x;
    int t = threadIdx.x;
    const float* row = X + (size_t)r * 512;
    float a = row[t], b = row[t + 256];
    float s = a * a + b * b;
    __shared__ float sm[256];
    sm[t] = s;
    __syncthreads();
    for (int o = 128; o > 0; o >>= 1) {
        if (t < o) sm[t] += sm[t + o];
        __syncthreads();
    }
    float inv = 1.0f / sqrtf(sm[0]);
    Y[(size_t)r * 512 + t]       = __float2half_rn(a * inv);
    Y[(size_t)r * 512 + t + 256] = __float2half_rn(b * inv);
}

__global__ void lse_kernel(const float* __restrict__ scale_ptr) {
    int r = blockIdx.x;
    int t = threadIdx.x;
    float s = scale_ptr[0];
    const float4* row4 = (const float4*)(g_logits + (size_t)r * ROWS_ALL);
    const int n4 = ROWS_ALL / 4;   // 4224

    float m = -1e30f;
    for (int j = t; j < n4; j += 256) {
        float4 v = row4[j];
        m = fmaxf(m, fmaxf(fmaxf(v.x, v.y), fmaxf(v.z, v.w)));
    }
    __shared__ float sm[256];
    sm[t] = m;
    __syncthreads();
    for (int o = 128; o > 0; o >>= 1) {
        if (t < o) sm[t] = fmaxf(sm[t], sm[t + o]);
        __syncthreads();
    }
    m = sm[0];
    __syncthreads();

    float sum = 0.0f;
    for (int j = t; j < n4; j += 256) {
        float4 v = row4[j];
        sum += expf(s * (v.x - m)) + expf(s * (v.y - m))
             + expf(s * (v.z - m)) + expf(s * (v.w - m));
    }
    sm[t] = sum;
    __syncthreads();
    for (int o = 128; o > 0; o >>= 1) {
        if (t < o) sm[t] += sm[t + o];
        __syncthreads();
    }
    if (t == 0) {
        float diag = g_logits[(size_t)r * ROWS_ALL + r];
        g_partial[r] = s * (diag - m) - logf(sm[0]);
    }
}

__global__ void final_kernel(float* __restrict__ out) {
    int t = threadIdx.x;
    __shared__ float sm[512];
    sm[t] = g_partial[t];
    __syncthreads();
    for (int o = 256; o > 0; o >>= 1) {
        if (t < o) sm[t] += sm[t + o];
        __syncthreads();
    }
    if (t == 0) out[0] = -sm[0] / (float)B_SZ;
}

// ===========================================================================
extern "C" void kernel_launch(void* const* d_in, const int* in_sizes, int n_in,
                              void* d_out, int out_size) {
    const float* imgs        = (const float*)d_in[0];
    const float* gps         = (const float*)d_in[1];
    const float* gallery     = (const float*)d_in[3];
    const float* W_img       = (const float*)d_in[4];
    const float* freqs       = (const float*)d_in[5];
    const float* W1          = (const float*)d_in[6];
    const float* b1          = (const float*)d_in[7];
    const float* W2          = (const float*)d_in[8];
    const float* b2          = (const float*)d_in[9];
    const float* logit_scale = (const float*)d_in[10];
    const int*   pool_idx    = (const int*)d_in[11];
    const int*   far_sel     = (const int*)d_in[12];
    const int*   perm        = (const int*)d_in[13];
    float* out = (float*)d_out;

    void *p_ffh, *p_hh, *p_emb, *p_embh, *p_img, *p_imgh, *p_imgsh;
    void *p_w1t, *p_w2t, *p_wit, *p_logits, *p_part;
    cudaGetSymbolAddress(&p_ffh, g_ff_h);
    cudaGetSymbolAddress(&p_hh, g_h_h);
    cudaGetSymbolAddress(&p_emb, g_emb);
    cudaGetSymbolAddress(&p_embh, g_emb_h);
    cudaGetSymbolAddress(&p_img, g_img);
    cudaGetSymbolAddress(&p_imgh, g_img_h);
    cudaGetSymbolAddress(&p_imgsh, g_imgs_h);
    cudaGetSymbolAddress(&p_w1t, g_w1t_h);
    cudaGetSymbolAddress(&p_w2t, g_w2t_h);
    cudaGetSymbolAddress(&p_wit, g_wit_h);
    cudaGetSymbolAddress(&p_logits, g_logits);
    cudaGetSymbolAddress(&p_part, g_imgpart);
    __half* ffh  = (__half*)p_ffh;
    __half* hh   = (__half*)p_hh;
    float*  embp = (float*)p_emb;
    __half* embh = (__half*)p_embh;
    float*  imgp = (float*)p_img;
    __half* imgh = (__half*)p_imgh;
    __half* imgsh= (__half*)p_imgsh;
    __half* w1t  = (__half*)p_w1t;
    __half* w2t  = (__half*)p_w2t;
    __half* wit  = (__half*)p_wit;
    float*  logp = (float*)p_logits;
    float*  partp= (float*)p_part;
    (void)logp;

    cudaFuncSetAttribute(gemm_h<0, float>,  cudaFuncAttributeMaxDynamicSharedMemorySize, GEMM_SMEM);
    cudaFuncSetAttribute(gemm_h<1, __half>, cudaFuncAttributeMaxDynamicSharedMemorySize, GEMM_SMEM);
    cudaFuncSetAttribute(gemm_h<2, float>,  cudaFuncAttributeMaxDynamicSharedMemorySize, GEMM_SMEM);

    select_kernel<<<B_SZ, 192>>>(gps, gallery, pool_idx, far_sel, perm);
    noise_kernel<<<Q_SZ / 256, 256>>>();
    ff_kernel<<<ROWS_ALL, 256>>>(freqs);

    transpose_half<<<dim3(H_DIM / 32, (2 * F_DIM) / 32), dim3(32, 8)>>>(W1, w1t, 2 * F_DIM, H_DIM);
    transpose_half<<<dim3(E_DIM / 32, H_DIM / 32), dim3(32, 8)>>>(W2, w2t, H_DIM, E_DIM);
    transpose_half<<<dim3(E_DIM / 32, D_IMG / 32), dim3(32, 8)>>>(W_img, wit, D_IMG, E_DIM);
    round_half<<<(B_SZ * D_IMG) / 256, 256>>>(imgs, imgsh);

    // h = relu(ff @ W1 + b1) -> fp16
    gemm_h<1, __half><<<dim3(H_DIM / 128, ROWS_ALL / 128, 1), 256, GEMM_SMEM>>>(
        ffh, w1t, hh, b1, ROWS_ALL, H_DIM, 2 * F_DIM, 2 * F_DIM, 2 * F_DIM);
    // emb = h @ W2 + b2 -> f32
    gemm_h<2, float><<<dim3(E_DIM / 128, ROWS_ALL / 128, 1), 256, GEMM_SMEM>>>(
        hh, w2t, embp, b2, ROWS_ALL, E_DIM, H_DIM, H_DIM, H_DIM);
    l2norm_half<<<ROWS_ALL, 256>>>(embp, embh);

    // img_emb partials: split-K x8
    gemm_h<0, float><<<dim3(E_DIM / 128, B_SZ / 128, IMG_SPLITS), 256, GEMM_SMEM>>>(
        imgsh, wit, partp, nullptr, B_SZ, E_DIM, D_IMG / IMG_SPLITS, D_IMG, D_IMG);
    reduce_img<<<(B_SZ * E_DIM) / 256, 256>>>();
    l2norm_half<<<B_SZ, 256>>>(imgp, imgh);

    // logits = img_emb @ emb^T -> f32
    gemm_h<0, float><<<dim3(ROWS_ALL / 128, B_SZ / 128, 1), 256, GEMM_SMEM>>>(
        imgh, embh, (float*)p_logits, nullptr, B_SZ, ROWS_ALL, E_DIM, E_DIM, E_DIM);

    lse_kernel<<<B_SZ, 256>>>(logit_scale);
    final_kernel<<<1, B_SZ>>>(out);
}